// round 3
// baseline (speedup 1.0000x reference)
#include <cuda_runtime.h>
#include <math.h>

#define B_   128
#define T_   256
#define L_   16
#define DW_  300
#define DC_  100
#define HC_  100
#define H_   300
#define NT_  3
#define NV_  101          // char vocab rows (NC+1)
#define EMB_ 500          // DW + 2*HC
#define GW_  1200         // 4*H
#define GC_  400          // 4*HC
#define BT_  32768        // B*T

// ---------------- static device scratch (no runtime allocation) ----------------
__device__ __align__(16) float g_emb[BT_ * EMB_];        // [B*T, 500] word_emb | h_fw | h_bw
__device__ __align__(16) float g_zx[2][BT_ * GW_];       // word x-projection per dir (gate-permuted)
__device__ __align__(16) float g_Wp[2][800 * GW_];       // permuted Ww (col jp = u*4+g)
__device__ __align__(16) float g_bwp[2][GW_];            // permuted word bias
__device__ __align__(16) float g_zcv[2][NV_ * GC_];      // char vocab x-proj (+bias, permuted)
__device__ __align__(16) float g_h[2][2][B_ * H_];       // [parity][dir] word h (double buffer)
__device__ __align__(16) float g_c[2][B_ * H_];          // word cell state

__device__ __forceinline__ float sigf(float x) {
    return __fdividef(1.f, 1.f + __expf(-x));
}
__device__ __forceinline__ float tanhfast(float x) {
    x = fminf(fmaxf(x, -15.f), 15.f);
    float e = __expf(2.f * x);
    return __fdividef(e - 1.f, e + 1.f);
}

// ---- K0: word embedding gather + zero-init word LSTM state ----
__global__ void k_embed(const int* __restrict__ word_ids,
                        const float* __restrict__ word_emb) {
    int i = blockIdx.x * blockDim.x + threadIdx.x;
    if (i < BT_ * DW_) {
        int n = i / DW_, u = i - n * DW_;
        g_emb[(long)n * EMB_ + u] = word_emb[(long)word_ids[n] * DW_ + u];
    }
    if (i < B_ * H_) {
        g_h[0][0][i] = 0.f; g_h[0][1][i] = 0.f;
        g_h[1][0][i] = 0.f; g_h[1][1][i] = 0.f;
        g_c[0][i] = 0.f;    g_c[1][i] = 0.f;
    }
}

// ---- K1: permute word weights/bias to gate-interleaved columns jp = u*4+g ----
__global__ void k_permW(const float* __restrict__ Wf, const float* __restrict__ bf,
                        const float* __restrict__ Wb, const float* __restrict__ bb) {
    int i = blockIdx.x * blockDim.x + threadIdx.x;
    if (i < 2 * GW_) {
        int d = i / GW_, jp = i % GW_;
        const float* bs = d ? bb : bf;
        g_bwp[d][jp] = bs[(jp & 3) * H_ + (jp >> 2)];
    }
    if (i >= 2 * 800 * GW_) return;
    int d  = i / (800 * GW_);
    int r  = (i / GW_) % 800;
    int jp = i % GW_;
    const float* W = d ? Wb : Wf;
    g_Wp[d][(long)r * GW_ + jp] = W[(long)r * GW_ + (jp & 3) * H_ + (jp >> 2)];
}

// ---- K2: char vocab x-projection: zcv[d][v][u*4+g] = char_emb[v] @ Wx + b ----
__global__ void k_zcv(const float* __restrict__ char_emb,
                      const float* __restrict__ Wf, const float* __restrict__ bf,
                      const float* __restrict__ Wb, const float* __restrict__ bb) {
    int v = blockIdx.x, d = blockIdx.y, jp = threadIdx.x;      // jp in [0,400)
    const float* W  = d ? Wb : Wf;
    const float* bs = d ? bb : bf;
    int col = (jp & 3) * HC_ + (jp >> 2);
    float acc = bs[col];
    for (int k = 0; k < DC_; k++)
        acc += char_emb[v * DC_ + k] * W[k * GC_ + col];
    g_zcv[d][v * GC_ + jp] = acc;
}

// ---- K3: char BiLSTM recurrence. 32 sequences/block, Wh permuted in shared. ----
__global__ __launch_bounds__(400, 1)
void k_char(const int* __restrict__ char_ids,
            const int* __restrict__ word_len,
            const float* __restrict__ Wf,
            const float* __restrict__ Wb) {
    int dir  = blockIdx.y;
    int seq0 = blockIdx.x * 32;
    const float* W = dir ? Wb : Wf;
    extern __shared__ float sm[];
    float* Ws = sm;                  // [DC_*GC_] = 40000 floats (160KB) permuted Wh
    float* hs = sm + DC_ * GC_;      // [32*HC_]  = 3200 floats
    __shared__ int slen[32];
    __shared__ int scid[32];
    int tid = threadIdx.x;           // 400 threads

    // Stage permuted Wh: Ws[k*400 + (u*4+g)] = W[(100+k)*400 + g*100+u]
    for (int i = tid; i < DC_ * GC_; i += 400) {
        int k = i / GC_, jp = i % GC_;
        Ws[i] = W[(DC_ + k) * GC_ + (jp & 3) * HC_ + (jp >> 2)];
    }
    if (tid < 32) slen[tid] = word_len[seq0 + tid];
    for (int i = tid; i < 32 * HC_; i += 400) hs[i] = 0.f;

    int q = tid / HC_;               // 0..3 -> owns sequences q*8 .. q*8+7
    int u = tid % HC_;               // hidden unit
    int jp0 = u * 4;
    float creg[8], hreg[8];
#pragma unroll
    for (int a = 0; a < 8; a++) { creg[a] = 0.f; hreg[a] = 0.f; }
    __syncthreads();

    for (int t = 0; t < L_; t++) {
        if (tid < 32) {
            int len = slen[tid];
            int tt = dir ? (len - 1 - t) : t;
            if (tt < 0) tt = 0;
            if (tt >= L_) tt = L_ - 1;
            scid[tid] = char_ids[(seq0 + tid) * L_ + tt];
        }
        __syncthreads();   // sync1: scid ready, prev-iter hs writes visible

        float acc[8][4];
#pragma unroll
        for (int a = 0; a < 8; a++) {
            acc[a][0] = 0.f; acc[a][1] = 0.f; acc[a][2] = 0.f; acc[a][3] = 0.f;
        }
        for (int k = 0; k < HC_; k++) {
            float4 w = *(const float4*)&Ws[k * GC_ + jp0];
#pragma unroll
            for (int a = 0; a < 8; a++) {
                float hv = hs[(q * 8 + a) * HC_ + k];
                acc[a][0] += hv * w.x; acc[a][1] += hv * w.y;
                acc[a][2] += hv * w.z; acc[a][3] += hv * w.w;
            }
        }
        // gate math (reads scid/zcv, own registers) before sync2
        float cn[8], hn[8]; bool up[8];
#pragma unroll
        for (int a = 0; a < 8; a++) {
            int s = q * 8 + a;
            up[a] = (t < slen[s]);
            float4 zx = *(const float4*)&g_zcv[dir][scid[s] * GC_ + jp0];
            float iv = zx.x + acc[a][0], jv = zx.y + acc[a][1];
            float fv = zx.z + acc[a][2], ov = zx.w + acc[a][3];
            float c2 = creg[a] * sigf(fv + 1.f) + sigf(iv) * tanhfast(jv);
            cn[a] = c2;
            hn[a] = sigf(ov) * tanhfast(c2);
        }
        __syncthreads();   // sync2: all hs reads (and scid reads) done
#pragma unroll
        for (int a = 0; a < 8; a++) {
            if (up[a]) {
                creg[a] = cn[a]; hreg[a] = hn[a];
                hs[(q * 8 + a) * HC_ + u] = hn[a];
            }
        }
    }
    // final h -> char_rep columns of g_emb
#pragma unroll
    for (int a = 0; a < 8; a++) {
        int n = seq0 + q * 8 + a;
        g_emb[(long)n * EMB_ + DW_ + dir * HC_ + u] = hreg[a];
    }
}

// ---- K4: word x-projection GEMM: g_zx[d][n][jp] = emb[n] @ Wx_perm + b_perm ----
// Tile: 64 rows (n) x 120 cols (30 unit-quads). 240 threads: uq = tid%30, ng = tid/30.
__global__ __launch_bounds__(240)
void k_xproj() {
    int dir = blockIdx.z;
    int n0  = blockIdx.x * 64;
    int c0  = blockIdx.y * 120;
    __shared__ __align__(16) float As[64 * 25];
    __shared__ __align__(16) float Bs[25 * 120];
    int tid = threadIdx.x;
    int uq = tid % 30, ng = tid / 30;
    float acc[8][4];
#pragma unroll
    for (int a = 0; a < 8; a++) { acc[a][0] = acc[a][1] = acc[a][2] = acc[a][3] = 0.f; }
    const float* Wp = g_Wp[dir];

    for (int kc = 0; kc < EMB_; kc += 25) {
        for (int i = tid; i < 64 * 25; i += 240) {
            int r = i / 25, kk = i % 25;
            As[i] = g_emb[(long)(n0 + r) * EMB_ + kc + kk];
        }
        for (int i = tid; i < 25 * 120; i += 240) {
            int k = i / 120, j = i % 120;
            Bs[i] = Wp[(long)(kc + k) * GW_ + c0 + j];
        }
        __syncthreads();
        for (int kk = 0; kk < 25; kk++) {
            float4 w = *(const float4*)&Bs[kk * 120 + uq * 4];
#pragma unroll
            for (int a = 0; a < 8; a++) {
                float av = As[(ng * 8 + a) * 25 + kk];
                acc[a][0] += av * w.x; acc[a][1] += av * w.y;
                acc[a][2] += av * w.z; acc[a][3] += av * w.w;
            }
        }
        __syncthreads();
    }
    float4 bv = *(const float4*)&g_bwp[dir][c0 + uq * 4];
#pragma unroll
    for (int a = 0; a < 8; a++) {
        int n = n0 + ng * 8 + a;
        float4 o;
        o.x = acc[a][0] + bv.x; o.y = acc[a][1] + bv.y;
        o.z = acc[a][2] + bv.z; o.w = acc[a][3] + bv.w;
        *(float4*)&g_zx[dir][(long)n * GW_ + c0 + uq * 4] = o;
    }
}

// ---- K5: one word-LSTM time step (both dirs). grid (15 utiles, 8 btiles, 2). ----
__global__ __launch_bounds__(320)
void k_step(const int* __restrict__ seqlen, int t) {
    int dir = blockIdx.z;
    int b0  = blockIdx.y * 16;
    int u0  = blockIdx.x * 20;
    int p   = t & 1;
    __shared__ float hsm[16 * H_];   // 19.2KB
    int tid = threadIdx.x;           // 320 = 20u x 16b
    for (int i = tid; i < 16 * H_; i += 320)
        hsm[i] = g_h[p][dir][(long)b0 * H_ + i];
    __syncthreads();

    int u  = u0 + tid % 20;
    int bl = tid / 20;
    int bg = b0 + bl;
    const float* Wh = g_Wp[dir] + (long)EMB_ * GW_;   // recurrent rows 500..799
    float a0 = 0.f, a1 = 0.f, a2 = 0.f, a3 = 0.f;
#pragma unroll 4
    for (int k = 0; k < H_; k++) {
        float4 w = *(const float4*)&Wh[(long)k * GW_ + u * 4];
        float hv = hsm[bl * H_ + k];
        a0 += hv * w.x; a1 += hv * w.y; a2 += hv * w.z; a3 += hv * w.w;
    }
    int len = seqlen[bg];
    int tt = dir ? ((t < len) ? (len - 1 - t) : t) : t;
    int n = bg * T_ + tt;
    float4 zx = *(const float4*)&g_zx[dir][(long)n * GW_ + u * 4];
    float iv = zx.x + a0, jv = zx.y + a1, fv = zx.z + a2, ov = zx.w + a3;
    int idx = bg * H_ + u;
    float cold = g_c[dir][idx];
    float hold = hsm[bl * H_ + u];
    float cnew = cold * sigf(fv + 1.f) + sigf(iv) * tanhfast(jv);
    float hnew = sigf(ov) * tanhfast(cnew);
    if (t >= len) { cnew = cold; hnew = hold; }
    g_c[dir][idx] = cnew;
    g_h[p ^ 1][dir][idx] = hnew;
}

// ---- K6: projection + log_softmax + NLL mean ----
__global__ void k_final(const int* __restrict__ labels,
                        const float* __restrict__ Wp,
                        const float* __restrict__ bp,
                        float* __restrict__ out) {
    __shared__ float red[128];
    int b = threadIdx.x;
    float l0 = bp[0], l1 = bp[1], l2 = bp[2];
    for (int k = 0; k < H_; k++) {
        float v = g_c[0][b * H_ + k];
        l0 += v * Wp[k * 3 + 0]; l1 += v * Wp[k * 3 + 1]; l2 += v * Wp[k * 3 + 2];
    }
    for (int k = 0; k < H_; k++) {
        float v = g_c[1][b * H_ + k];
        l0 += v * Wp[(H_ + k) * 3 + 0]; l1 += v * Wp[(H_ + k) * 3 + 1]; l2 += v * Wp[(H_ + k) * 3 + 2];
    }
    float m = fmaxf(l0, fmaxf(l1, l2));
    float lse = m + logf(expf(l0 - m) + expf(l1 - m) + expf(l2 - m));
    int lab = labels[b];
    float lp = ((lab == 0) ? l0 : (lab == 1) ? l1 : l2) - lse;
    red[b] = lp;
    __syncthreads();
    for (int s = 64; s > 0; s >>= 1) {
        if (b < s) red[b] += red[b + s];
        __syncthreads();
    }
    if (b == 0) out[0] = -red[0] / 128.f;
}

extern "C" void kernel_launch(void* const* d_in, const int* in_sizes, int n_in,
                              void* d_out, int out_size) {
    (void)in_sizes; (void)n_in; (void)out_size;
    const int*   word_ids = (const int*)  d_in[0];
    const int*   seq_len  = (const int*)  d_in[1];
    const int*   char_ids = (const int*)  d_in[2];
    const int*   word_len = (const int*)  d_in[3];
    const int*   labels   = (const int*)  d_in[4];
    const float* word_emb = (const float*)d_in[5];
    const float* char_emb = (const float*)d_in[6];
    const float* Wc_fw    = (const float*)d_in[7];
    const float* bc_fw    = (const float*)d_in[8];
    const float* Wc_bw    = (const float*)d_in[9];
    const float* bc_bw    = (const float*)d_in[10];
    const float* Ww_fw    = (const float*)d_in[11];
    const float* bw_fw    = (const float*)d_in[12];
    const float* Ww_bw    = (const float*)d_in[13];
    const float* bw_bw    = (const float*)d_in[14];
    const float* W_proj   = (const float*)d_in[15];
    const float* b_proj   = (const float*)d_in[16];
    float* out = (float*)d_out;

    int char_smem = (DC_ * GC_ + 32 * HC_) * 4;   // 172800 bytes
    cudaFuncSetAttribute(k_char, cudaFuncAttributeMaxDynamicSharedMemorySize, char_smem);

    k_embed<<<(BT_ * DW_ + 255) / 256, 256>>>(word_ids, word_emb);
    k_permW<<<(2 * 800 * GW_ + 255) / 256, 256>>>(Ww_fw, bw_fw, Ww_bw, bw_bw);
    k_zcv<<<dim3(NV_, 2), GC_>>>(char_emb, Wc_fw, bc_fw, Wc_bw, bc_bw);
    k_char<<<dim3(BT_ / 32, 2), 400, char_smem>>>(char_ids, word_len, Wc_fw, Wc_bw);
    k_xproj<<<dim3(BT_ / 64, 10, 2), 240>>>();
    for (int t = 0; t < T_; t++)
        k_step<<<dim3(15, 8, 2), 320>>>(seq_len, t);
    k_final<<<1, 128>>>(labels, W_proj, b_proj, out);
}

// round 4
// speedup vs baseline: 1.0454x; 1.0454x over previous
#include <cuda_runtime.h>
#include <math.h>

#define B_   128
#define T_   256
#define L_   16
#define DW_  300
#define DC_  100
#define HC_  100
#define H_   300
#define NT_  3
#define NV_  101          // char vocab rows (NC+1)
#define EMB_ 500          // DW + 2*HC
#define GW_  1200         // 4*H
#define GC_  400          // 4*HC
#define BT_  32768        // B*T

// ---------------- static device scratch (no runtime allocation) ----------------
__device__ __align__(16) float g_emb[BT_ * EMB_];        // [B*T, 500] word_emb | h_fw | h_bw
__device__ __align__(16) float g_zx[2][BT_ * GW_];       // word x-projection per dir (gate-permuted)
__device__ __align__(16) float g_Wp[2][800 * GW_];       // permuted Ww (col jp = u*4+g)
__device__ __align__(16) float g_bwp[2][GW_];            // permuted word bias
__device__ __align__(16) float g_zcv[2][NV_ * GC_];      // char vocab x-proj (+bias, permuted)
__device__ __align__(16) float g_h[2][2][B_ * H_];       // [parity][dir] word h (double buffer)
__device__ __align__(16) float g_c[2][B_ * H_];          // word cell state

__device__ __forceinline__ float sigf(float x) {
    return __fdividef(1.f, 1.f + __expf(-x));
}
__device__ __forceinline__ float tanhfast(float x) {
    x = fminf(fmaxf(x, -15.f), 15.f);
    float e = __expf(2.f * x);
    return __fdividef(e - 1.f, e + 1.f);
}

// ---- K0: word embedding gather (float4) + zero-init word LSTM state ----
__global__ void k_embed(const int* __restrict__ word_ids,
                        const float* __restrict__ word_emb) {
    int i = blockIdx.x * blockDim.x + threadIdx.x;
    if (i < BT_ * 75) {                         // 75 float4 per row of DW_=300
        int n = i / 75, uq = i % 75;
        *(float4*)&g_emb[(long)n * EMB_ + uq * 4] =
            *(const float4*)&word_emb[(long)word_ids[n] * DW_ + uq * 4];
    }
    if (i < B_ * H_) {
        g_h[0][0][i] = 0.f; g_h[0][1][i] = 0.f;
        g_h[1][0][i] = 0.f; g_h[1][1][i] = 0.f;
        g_c[0][i] = 0.f;    g_c[1][i] = 0.f;
    }
}

// ---- K1: permute word weights/bias to gate-interleaved columns jp = u*4+g ----
__global__ void k_permW(const float* __restrict__ Wf, const float* __restrict__ bf,
                        const float* __restrict__ Wb, const float* __restrict__ bb) {
    int i = blockIdx.x * blockDim.x + threadIdx.x;
    if (i < 2 * GW_) {
        int d = i / GW_, jp = i % GW_;
        const float* bs = d ? bb : bf;
        g_bwp[d][jp] = bs[(jp & 3) * H_ + (jp >> 2)];
    }
    if (i >= 2 * 800 * GW_) return;
    int d  = i / (800 * GW_);
    int r  = (i / GW_) % 800;
    int jp = i % GW_;
    const float* W = d ? Wb : Wf;
    g_Wp[d][(long)r * GW_ + jp] = W[(long)r * GW_ + (jp & 3) * H_ + (jp >> 2)];
}

// ---- K2: char vocab x-projection: zcv[d][v][u*4+g] = char_emb[v] @ Wx + b ----
__global__ void k_zcv(const float* __restrict__ char_emb,
                      const float* __restrict__ Wf, const float* __restrict__ bf,
                      const float* __restrict__ Wb, const float* __restrict__ bb) {
    int v = blockIdx.x, d = blockIdx.y, jp = threadIdx.x;      // jp in [0,400)
    const float* W  = d ? Wb : Wf;
    const float* bs = d ? bb : bf;
    int col = (jp & 3) * HC_ + (jp >> 2);
    float acc = bs[col];
    for (int k = 0; k < DC_; k++)
        acc += char_emb[v * DC_ + k] * W[k * GC_ + col];
    g_zcv[d][v * GC_ + jp] = acc;
}

// ---- K3: char BiLSTM recurrence. 32 sequences/block, Wh permuted in shared,
//          double-buffered h, k-unrolled x4 with float4 h loads. ----
__global__ __launch_bounds__(400, 1)
void k_char(const int* __restrict__ char_ids,
            const int* __restrict__ word_len,
            const float* __restrict__ Wf,
            const float* __restrict__ Wb) {
    int dir  = blockIdx.y;
    int seq0 = blockIdx.x * 32;
    const float* W = dir ? Wb : Wf;
    extern __shared__ float sm[];
    float* Ws  = sm;                         // [DC_*GC_] 40000 floats (160KB)
    float* hsA = sm + DC_ * GC_;             // [32*HC_] 3200 floats
    float* hsB = hsA + 32 * HC_;             // [32*HC_] 3200 floats
    __shared__ int slen[32];
    __shared__ int scid[L_][32];
    int tid = threadIdx.x;                   // 400 threads

    // Stage permuted Wh: Ws[k*400 + (u*4+g)] = W[(100+k)*400 + g*100+u]
    for (int i = tid; i < DC_ * GC_; i += 400) {
        int k = i / GC_, jp = i % GC_;
        Ws[i] = W[(DC_ + k) * GC_ + (jp & 3) * HC_ + (jp >> 2)];
    }
    for (int i = tid; i < 32 * HC_; i += 400) hsA[i] = 0.f;
    if (tid < 32) {
        int len = word_len[seq0 + tid];
        slen[tid] = len;
#pragma unroll
        for (int t = 0; t < L_; t++) {
            int tt = dir ? (len - 1 - t) : t;
            if (tt < 0) tt = 0;
            if (tt >= L_) tt = L_ - 1;
            scid[t][tid] = char_ids[(seq0 + tid) * L_ + tt];
        }
    }

    int q = tid / HC_;               // owns sequences q*8 .. q*8+7
    int u = tid % HC_;
    int jp0 = u * 4;
    float creg[8], hreg[8];
#pragma unroll
    for (int a = 0; a < 8; a++) { creg[a] = 0.f; hreg[a] = 0.f; }
    float* hr = hsA;
    float* hw = hsB;
    __syncthreads();

    for (int t = 0; t < L_; t++) {
        float acc[8][4];
#pragma unroll
        for (int a = 0; a < 8; a++) {
            acc[a][0] = 0.f; acc[a][1] = 0.f; acc[a][2] = 0.f; acc[a][3] = 0.f;
        }
#pragma unroll 5
        for (int k = 0; k < HC_; k += 4) {
            float4 w0 = *(const float4*)&Ws[(k    ) * GC_ + jp0];
            float4 w1 = *(const float4*)&Ws[(k + 1) * GC_ + jp0];
            float4 w2 = *(const float4*)&Ws[(k + 2) * GC_ + jp0];
            float4 w3 = *(const float4*)&Ws[(k + 3) * GC_ + jp0];
#pragma unroll
            for (int a = 0; a < 8; a++) {
                float4 hv = *(const float4*)&hr[(q * 8 + a) * HC_ + k];
                acc[a][0] += hv.x * w0.x + hv.y * w1.x + hv.z * w2.x + hv.w * w3.x;
                acc[a][1] += hv.x * w0.y + hv.y * w1.y + hv.z * w2.y + hv.w * w3.y;
                acc[a][2] += hv.x * w0.z + hv.y * w1.z + hv.z * w2.z + hv.w * w3.z;
                acc[a][3] += hv.x * w0.w + hv.y * w1.w + hv.z * w2.w + hv.w * w3.w;
            }
        }
#pragma unroll
        for (int a = 0; a < 8; a++) {
            int s = q * 8 + a;
            float4 zx = *(const float4*)&g_zcv[dir][scid[t][s] * GC_ + jp0];
            float iv = zx.x + acc[a][0], jv = zx.y + acc[a][1];
            float fv = zx.z + acc[a][2], ov = zx.w + acc[a][3];
            float c2 = creg[a] * sigf(fv + 1.f) + sigf(iv) * tanhfast(jv);
            float h2 = sigf(ov) * tanhfast(c2);
            if (t < slen[s]) { creg[a] = c2; hreg[a] = h2; }
            hw[s * HC_ + u] = hreg[a];      // writes go to the OTHER buffer
        }
        __syncthreads();                    // publish hw for next step's reads
        float* tmp = hr; hr = hw; hw = tmp;
    }
    // final h -> char_rep columns of g_emb
#pragma unroll
    for (int a = 0; a < 8; a++) {
        int n = seq0 + q * 8 + a;
        g_emb[(long)n * EMB_ + DW_ + dir * HC_ + u] = hreg[a];
    }
}

// ---- K4: word x-projection GEMM: g_zx[d][n][jp] = emb[n] @ Wx_perm + b_perm ----
// Tile: 64 rows x 120 cols, k-chunk 20, inner unroll x4 with float4 A loads.
__global__ __launch_bounds__(240)
void k_xproj() {
    int dir = blockIdx.z;
    int n0  = blockIdx.x * 64;
    int c0  = blockIdx.y * 120;
    __shared__ __align__(16) float As[64 * 20];
    __shared__ __align__(16) float Bs[20 * 120];
    int tid = threadIdx.x;
    int uq = tid % 30, ng = tid / 30;
    float acc[8][4];
#pragma unroll
    for (int a = 0; a < 8; a++) { acc[a][0] = acc[a][1] = acc[a][2] = acc[a][3] = 0.f; }
    const float* Wp = g_Wp[dir];

    for (int kc = 0; kc < EMB_; kc += 20) {
        // stage A: 64 rows x 5 float4
        for (int i = tid; i < 64 * 5; i += 240) {
            int r = i / 5, kq = i % 5;
            ((float4*)As)[i] = *(const float4*)&g_emb[(long)(n0 + r) * EMB_ + kc + kq * 4];
        }
        // stage B: 20 rows x 30 float4
        for (int i = tid; i < 20 * 30; i += 240) {
            int r = i / 30, jq = i % 30;
            ((float4*)Bs)[i] = *(const float4*)&Wp[(long)(kc + r) * GW_ + c0 + jq * 4];
        }
        __syncthreads();
#pragma unroll
        for (int kk = 0; kk < 20; kk += 4) {
            float4 w0 = *(const float4*)&Bs[(kk    ) * 120 + uq * 4];
            float4 w1 = *(const float4*)&Bs[(kk + 1) * 120 + uq * 4];
            float4 w2 = *(const float4*)&Bs[(kk + 2) * 120 + uq * 4];
            float4 w3 = *(const float4*)&Bs[(kk + 3) * 120 + uq * 4];
#pragma unroll
            for (int a = 0; a < 8; a++) {
                float4 av = *(const float4*)&As[(ng * 8 + a) * 20 + kk];
                acc[a][0] += av.x * w0.x + av.y * w1.x + av.z * w2.x + av.w * w3.x;
                acc[a][1] += av.x * w0.y + av.y * w1.y + av.z * w2.y + av.w * w3.y;
                acc[a][2] += av.x * w0.z + av.y * w1.z + av.z * w2.z + av.w * w3.z;
                acc[a][3] += av.x * w0.w + av.y * w1.w + av.z * w2.w + av.w * w3.w;
            }
        }
        __syncthreads();
    }
    float4 bv = *(const float4*)&g_bwp[dir][c0 + uq * 4];
#pragma unroll
    for (int a = 0; a < 8; a++) {
        int n = n0 + ng * 8 + a;
        float4 o;
        o.x = acc[a][0] + bv.x; o.y = acc[a][1] + bv.y;
        o.z = acc[a][2] + bv.z; o.w = acc[a][3] + bv.w;
        *(float4*)&g_zx[dir][(long)n * GW_ + c0 + uq * 4] = o;
    }
}

// ---- K5: one word-LSTM step. 160 thr = 20 units x 8 batch-pairs (2 batches each). ----
__global__ __launch_bounds__(160)
void k_step(const int* __restrict__ seqlen, int t) {
    int dir = blockIdx.z;
    int b0  = blockIdx.y * 16;
    int u0  = blockIdx.x * 20;
    int p   = t & 1;
    __shared__ float hsm[16 * H_];   // 19.2KB
    int tid = threadIdx.x;           // 160
    for (int i = tid; i < 16 * H_; i += 160)
        hsm[i] = g_h[p][dir][(long)b0 * H_ + i];
    __syncthreads();

    int u   = u0 + tid % 20;
    int bp  = tid / 20;              // 0..7
    int bl0 = bp * 2, bl1 = bp * 2 + 1;
    const float* Wh = g_Wp[dir] + (long)EMB_ * GW_;   // recurrent rows 500..799
    float a00 = 0.f, a01 = 0.f, a02 = 0.f, a03 = 0.f;
    float a10 = 0.f, a11 = 0.f, a12 = 0.f, a13 = 0.f;
#pragma unroll 4
    for (int k = 0; k < H_; k++) {
        float4 w = *(const float4*)&Wh[(long)k * GW_ + u * 4];
        float h0 = hsm[bl0 * H_ + k];
        float h1 = hsm[bl1 * H_ + k];
        a00 += h0 * w.x; a01 += h0 * w.y; a02 += h0 * w.z; a03 += h0 * w.w;
        a10 += h1 * w.x; a11 += h1 * w.y; a12 += h1 * w.z; a13 += h1 * w.w;
    }
#pragma unroll
    for (int pi = 0; pi < 2; pi++) {
        int bl = bp * 2 + pi;
        int bg = b0 + bl;
        float A0 = pi ? a10 : a00, A1 = pi ? a11 : a01;
        float A2 = pi ? a12 : a02, A3 = pi ? a13 : a03;
        int len = seqlen[bg];
        int tt = dir ? ((t < len) ? (len - 1 - t) : t) : t;
        int n = bg * T_ + tt;
        float4 zx = *(const float4*)&g_zx[dir][(long)n * GW_ + u * 4];
        float iv = zx.x + A0, jv = zx.y + A1, fv = zx.z + A2, ov = zx.w + A3;
        int idx = bg * H_ + u;
        float cold = g_c[dir][idx];
        float hold = hsm[bl * H_ + u];
        float cnew = cold * sigf(fv + 1.f) + sigf(iv) * tanhfast(jv);
        float hnew = sigf(ov) * tanhfast(cnew);
        if (t >= len) { cnew = cold; hnew = hold; }
        g_c[dir][idx] = cnew;
        g_h[p ^ 1][dir][idx] = hnew;
    }
}

// ---- K6: projection + log_softmax + NLL mean ----
__global__ void k_final(const int* __restrict__ labels,
                        const float* __restrict__ Wp,
                        const float* __restrict__ bp,
                        float* __restrict__ out) {
    __shared__ float red[128];
    int b = threadIdx.x;
    float l0 = bp[0], l1 = bp[1], l2 = bp[2];
    for (int k = 0; k < H_; k++) {
        float v = g_c[0][b * H_ + k];
        l0 += v * Wp[k * 3 + 0]; l1 += v * Wp[k * 3 + 1]; l2 += v * Wp[k * 3 + 2];
    }
    for (int k = 0; k < H_; k++) {
        float v = g_c[1][b * H_ + k];
        l0 += v * Wp[(H_ + k) * 3 + 0]; l1 += v * Wp[(H_ + k) * 3 + 1]; l2 += v * Wp[(H_ + k) * 3 + 2];
    }
    float m = fmaxf(l0, fmaxf(l1, l2));
    float lse = m + logf(expf(l0 - m) + expf(l1 - m) + expf(l2 - m));
    int lab = labels[b];
    float lp = ((lab == 0) ? l0 : (lab == 1) ? l1 : l2) - lse;
    red[b] = lp;
    __syncthreads();
    for (int s = 64; s > 0; s >>= 1) {
        if (b < s) red[b] += red[b + s];
        __syncthreads();
    }
    if (b == 0) out[0] = -red[0] / 128.f;
}

extern "C" void kernel_launch(void* const* d_in, const int* in_sizes, int n_in,
                              void* d_out, int out_size) {
    (void)in_sizes; (void)n_in; (void)out_size;
    const int*   word_ids = (const int*)  d_in[0];
    const int*   seq_len  = (const int*)  d_in[1];
    const int*   char_ids = (const int*)  d_in[2];
    const int*   word_len = (const int*)  d_in[3];
    const int*   labels   = (const int*)  d_in[4];
    const float* word_emb = (const float*)d_in[5];
    const float* char_emb = (const float*)d_in[6];
    const float* Wc_fw    = (const float*)d_in[7];
    const float* bc_fw    = (const float*)d_in[8];
    const float* Wc_bw    = (const float*)d_in[9];
    const float* bc_bw    = (const float*)d_in[10];
    const float* Ww_fw    = (const float*)d_in[11];
    const float* bw_fw    = (const float*)d_in[12];
    const float* Ww_bw    = (const float*)d_in[13];
    const float* bw_bw    = (const float*)d_in[14];
    const float* W_proj   = (const float*)d_in[15];
    const float* b_proj   = (const float*)d_in[16];
    float* out = (float*)d_out;

    int char_smem = (DC_ * GC_ + 2 * 32 * HC_) * 4;   // 160KB Wh + 2x12.8KB h = 185600B
    cudaFuncSetAttribute(k_char, cudaFuncAttributeMaxDynamicSharedMemorySize, char_smem);

    k_embed<<<(BT_ * 75 + 255) / 256, 256>>>(word_ids, word_emb);
    k_permW<<<(2 * 800 * GW_ + 255) / 256, 256>>>(Ww_fw, bw_fw, Ww_bw, bw_bw);
    k_zcv<<<dim3(NV_, 2), GC_>>>(char_emb, Wc_fw, bc_fw, Wc_bw, bc_bw);
    k_char<<<dim3(BT_ / 32, 2), 400, char_smem>>>(char_ids, word_len, Wc_fw, Wc_bw);
    k_xproj<<<dim3(BT_ / 64, 10, 2), 240>>>();
    for (int t = 0; t < T_; t++)
        k_step<<<dim3(15, 8, 2), 160>>>(seq_len, t);
    k_final<<<1, 128>>>(labels, W_proj, b_proj, out);
}

// round 7
// speedup vs baseline: 1.1377x; 1.0883x over previous
#include <cuda_runtime.h>
#include <cuda_bf16.h>
#include <cstdint>
#include <math.h>

#define B_   128
#define T_   256
#define L_   16
#define DW_  300
#define DC_  100
#define HC_  100
#define H_   300
#define NT_  3
#define NV_  101          // char vocab rows (NC+1)
#define EMB_ 500          // DW + 2*HC
#define KP_  512          // padded K for MMA
#define GW_  1200         // 4*H
#define GC_  400          // 4*HC
#define BT_  32768        // B*T

// ---------------- static device scratch (no runtime allocation) ----------------
__device__ __align__(16) float g_emb[BT_ * EMB_];        // [B*T, 500] word_emb | h_fw | h_bw
__device__ __align__(16) float g_zx[2][BT_ * GW_];       // word x-projection per dir (gate-permuted)
__device__ __align__(16) float g_Wp[2][800 * GW_];       // permuted Ww (col jp = u*4+g)
__device__ __align__(16) float g_bwp[2][GW_];            // permuted word bias
__device__ __align__(16) float g_zcv[2][NV_ * GC_];      // char vocab x-proj (+bias, permuted)
__device__ __align__(16) float g_h[2][2][B_ * H_];       // [parity][dir] word h (double buffer)
__device__ __align__(16) float g_c[2][B_ * H_];          // word cell state
// bf16 hi/lo operands for the x-projection MMA
__device__ __align__(16) __nv_bfloat16 g_Ahi[BT_ * KP_];
__device__ __align__(16) __nv_bfloat16 g_Alo[BT_ * KP_];
__device__ __align__(16) __nv_bfloat16 g_Bhi[2][GW_ * KP_];   // row jp, K-major
__device__ __align__(16) __nv_bfloat16 g_Blo[2][GW_ * KP_];

__device__ __forceinline__ float sigf(float x) {
    return __fdividef(1.f, 1.f + __expf(-x));
}
__device__ __forceinline__ float tanhfast(float x) {
    x = fminf(fmaxf(x, -15.f), 15.f);
    float e = __expf(2.f * x);
    return __fdividef(e - 1.f, e + 1.f);
}

// ---------------- warp-level MMA helpers (base ISA: sm_80 ldmatrix/HMMA) ----------------
__device__ __forceinline__ uint32_t smem_u32(const void* p) {
    uint32_t a;
    asm("{ .reg .u64 t; cvta.to.shared.u64 t, %1; cvt.u32.u64 %0, t; }" : "=r"(a) : "l"(p));
    return a;
}
#define LDSM_X4(r0, r1, r2, r3, addr) \
    asm volatile("ldmatrix.sync.aligned.m8n8.x4.shared.b16 {%0,%1,%2,%3}, [%4];" \
                 : "=r"(r0), "=r"(r1), "=r"(r2), "=r"(r3) : "r"(addr))
#define LDSM_X2(r0, r1, addr) \
    asm volatile("ldmatrix.sync.aligned.m8n8.x2.shared.b16 {%0,%1}, [%2];" \
                 : "=r"(r0), "=r"(r1) : "r"(addr))
#define MMA16816(c, a, b) \
    asm volatile("mma.sync.aligned.m16n8k16.row.col.f32.bf16.bf16.f32 " \
                 "{%0,%1,%2,%3}, {%4,%5,%6,%7}, {%8,%9}, {%0,%1,%2,%3};" \
                 : "+f"((c)[0]), "+f"((c)[1]), "+f"((c)[2]), "+f"((c)[3]) \
                 : "r"((a)[0]), "r"((a)[1]), "r"((a)[2]), "r"((a)[3]), \
                   "r"((b)[0]), "r"((b)[1]))

// ---- K0: word embedding gather (float4) + zero-init word LSTM state ----
__global__ void k_embed(const int* __restrict__ word_ids,
                        const float* __restrict__ word_emb) {
    int i = blockIdx.x * blockDim.x + threadIdx.x;
    if (i < BT_ * 75) {
        int n = i / 75, uq = i % 75;
        *(float4*)&g_emb[(long)n * EMB_ + uq * 4] =
            *(const float4*)&word_emb[(long)word_ids[n] * DW_ + uq * 4];
    }
    if (i < B_ * H_) {
        g_h[0][0][i] = 0.f; g_h[0][1][i] = 0.f;
        g_h[1][0][i] = 0.f; g_h[1][1][i] = 0.f;
        g_c[0][i] = 0.f;    g_c[1][i] = 0.f;
    }
}

// ---- K1: permute word weights/bias to gate-interleaved columns jp = u*4+g ----
__global__ void k_permW(const float* __restrict__ Wf, const float* __restrict__ bf,
                        const float* __restrict__ Wb, const float* __restrict__ bb) {
    int i = blockIdx.x * blockDim.x + threadIdx.x;
    if (i < 2 * GW_) {
        int d = i / GW_, jp = i % GW_;
        const float* bs = d ? bb : bf;
        g_bwp[d][jp] = bs[(jp & 3) * H_ + (jp >> 2)];
    }
    if (i >= 2 * 800 * GW_) return;
    int d  = i / (800 * GW_);
    int r  = (i / GW_) % 800;
    int jp = i % GW_;
    const float* W = d ? Wb : Wf;
    g_Wp[d][(long)r * GW_ + jp] = W[(long)r * GW_ + (jp & 3) * H_ + (jp >> 2)];
}

// ---- K1b: bf16 hi/lo of word W (x-rows only), row jp, K-major ----
__global__ void k_W2bf(const float* __restrict__ Wf, const float* __restrict__ Wb) {
    int i = blockIdx.x * blockDim.x + threadIdx.x;
    if (i >= 2 * GW_ * KP_) return;
    int d  = i / (GW_ * KP_);
    int jp = (i / KP_) % GW_;
    int k  = i % KP_;
    float v = 0.f;
    if (k < EMB_) {
        const float* W = d ? Wb : Wf;
        v = W[(long)k * GW_ + (jp & 3) * H_ + (jp >> 2)];
    }
    __nv_bfloat16 hi = __float2bfloat16(v);
    __nv_bfloat16 lo = __float2bfloat16(v - __bfloat162float(hi));
    g_Bhi[d][(long)jp * KP_ + k] = hi;
    g_Blo[d][(long)jp * KP_ + k] = lo;
}

// ---- K2: char vocab x-projection ----
__global__ void k_zcv(const float* __restrict__ char_emb,
                      const float* __restrict__ Wf, const float* __restrict__ bf,
                      const float* __restrict__ Wb, const float* __restrict__ bb) {
    int v = blockIdx.x, d = blockIdx.y, jp = threadIdx.x;
    const float* W  = d ? Wb : Wf;
    const float* bs = d ? bb : bf;
    int col = (jp & 3) * HC_ + (jp >> 2);
    float acc = bs[col];
    for (int k = 0; k < DC_; k++)
        acc += char_emb[v * DC_ + k] * W[k * GC_ + col];
    g_zcv[d][v * GC_ + jp] = acc;
}

// ---- K3: char BiLSTM recurrence. lane = sequence, warp = unit-group. ----
// h stored transposed hs[k*33 + s]: w loads warp-broadcast, h loads conflict-free.
__global__ __launch_bounds__(800, 1)
void k_char(const int* __restrict__ char_ids,
            const int* __restrict__ word_len,
            const float* __restrict__ Wf,
            const float* __restrict__ Wb) {
    int dir  = blockIdx.y;
    int seq0 = blockIdx.x * 32;
    const float* W = dir ? Wb : Wf;
    extern __shared__ float sm[];
    float* Ws  = sm;                         // [100*400] permuted Wh (160KB)
    float* hsA = sm + 40000;                 // [100*33] transposed h
    float* hsB = hsA + 3300;
    __shared__ int slen[32];
    __shared__ int scid[L_][32];
    int tid = threadIdx.x;                   // 800 = 25 uu x 32 s

    for (int i = tid; i < DC_ * GC_; i += 800) {
        int k = i / GC_, jp = i % GC_;
        Ws[i] = W[(DC_ + k) * GC_ + (jp & 3) * HC_ + (jp >> 2)];
    }
    for (int i = tid; i < 3300; i += 800) hsA[i] = 0.f;
    if (tid < 32) {
        int len = word_len[seq0 + tid];
        slen[tid] = len;
#pragma unroll
        for (int t = 0; t < L_; t++) {
            int tt = dir ? (len - 1 - t) : t;
            if (tt < 0) tt = 0;
            if (tt >= L_) tt = L_ - 1;
            scid[t][tid] = char_ids[(seq0 + tid) * L_ + tt];
        }
    }

    int s  = tid & 31;               // sequence within block
    int uu = tid >> 5;               // 0..24, owns units uu*4 .. uu*4+3
    int u0 = uu * 4;
    float creg[4] = {0.f, 0.f, 0.f, 0.f};
    float hreg[4] = {0.f, 0.f, 0.f, 0.f};
    float* hr = hsA;
    float* hw = hsB;
    __syncthreads();

    for (int t = 0; t < L_; t++) {
        float acc[4][4];
#pragma unroll
        for (int j = 0; j < 4; j++) {
            acc[j][0] = 0.f; acc[j][1] = 0.f; acc[j][2] = 0.f; acc[j][3] = 0.f;
        }
#pragma unroll 2
        for (int k = 0; k < HC_; k++) {
            float hv = hr[k * 33 + s];
#pragma unroll
            for (int j = 0; j < 4; j++) {
                float4 w = *(const float4*)&Ws[k * GC_ + (u0 + j) * 4];
                acc[j][0] += hv * w.x; acc[j][1] += hv * w.y;
                acc[j][2] += hv * w.z; acc[j][3] += hv * w.w;
            }
        }
        int len = slen[s], cid = scid[t][s];
#pragma unroll
        for (int j = 0; j < 4; j++) {
            float4 zx = *(const float4*)&g_zcv[dir][cid * GC_ + (u0 + j) * 4];
            float iv = zx.x + acc[j][0], jv = zx.y + acc[j][1];
            float fv = zx.z + acc[j][2], ov = zx.w + acc[j][3];
            float c2 = creg[j] * sigf(fv + 1.f) + sigf(iv) * tanhfast(jv);
            float h2 = sigf(ov) * tanhfast(c2);
            if (t < len) { creg[j] = c2; hreg[j] = h2; }
            hw[(u0 + j) * 33 + s] = hreg[j];
        }
        __syncthreads();
        float* tmp = hr; hr = hw; hw = tmp;
    }
#pragma unroll
    for (int j = 0; j < 4; j++)
        g_emb[(long)(seq0 + s) * EMB_ + DW_ + dir * HC_ + u0 + j] = hreg[j];
}

// ---- K3b: split emb rows into bf16 hi/lo (padded K=512) ----
__global__ void k_emb2bf() {
    long i = (long)blockIdx.x * blockDim.x + threadIdx.x;
    if (i >= (long)BT_ * KP_) return;
    long n = i / KP_;
    int  k = (int)(i % KP_);
    float v = (k < EMB_) ? g_emb[n * EMB_ + k] : 0.f;
    __nv_bfloat16 hi = __float2bfloat16(v);
    __nv_bfloat16 lo = __float2bfloat16(v - __bfloat162float(hi));
    g_Ahi[i] = hi;
    g_Alo[i] = lo;
}

// ---- K4: x-projection via mma.sync bf16 hi/lo (3-pass). Block 128M x 80N. ----
// 256 thr = 8 warps (4M x 2N); warp tile 32M x 40N = 2 m16 x 5 n8 frags.
// K chunk 64, smem rows padded to 72 bf16 (144B) -> conflict-free ldmatrix.
#define XSTR 72
#define XOF_AHI 0
#define XOF_ALO 18432
#define XOF_BHI 36864
#define XOF_BLO 48384
#define XOF_BIAS 59904
#define X_SMEM  (XOF_BIAS + 320)

__global__ __launch_bounds__(256, 2)
void k_xmma() {
    extern __shared__ char smc[];
    int dir = blockIdx.z;
    int m0  = blockIdx.x * 128;
    int c0  = blockIdx.y * 80;
    int tid = threadIdx.x;
    int wid = tid >> 5, lane = tid & 31;
    int wm = wid & 3, wn = wid >> 2;         // 4 M-warps x 2 N-warps
    float* sbias = (float*)(smc + XOF_BIAS);

    for (int i = tid; i < 80; i += 256) sbias[i] = g_bwp[dir][c0 + i];

    uint32_t sb = smem_u32(smc);
    int r  = lane & 7, mi = lane >> 3;
    // ldmatrix per-lane offsets (elements)
    int aRow = wm * 32 + (mi & 1) * 8 + r;   // + fm*16
    int aCol = (mi >> 1) * 8;                // + kk
    int bRow = wn * 40 + r;                  // + fn*8
    int bCol = (mi & 1) * 8;                 // + kk
    uint32_t aOff = (uint32_t)(aRow * XSTR + aCol) * 2;
    uint32_t bOff = (uint32_t)(bRow * XSTR + bCol) * 2;

    float acc[2][5][4];
#pragma unroll
    for (int fm = 0; fm < 2; fm++)
#pragma unroll
        for (int fn = 0; fn < 5; fn++) {
            acc[fm][fn][0] = 0.f; acc[fm][fn][1] = 0.f;
            acc[fm][fn][2] = 0.f; acc[fm][fn][3] = 0.f;
        }

    const __nv_bfloat16* gBh = g_Bhi[dir];
    const __nv_bfloat16* gBl = g_Blo[dir];

    for (int ch = 0; ch < 8; ch++) {
        int kc = ch * 64;
        __syncthreads();                     // previous chunk's compute done
        // stage A hi/lo: 128 rows x 8 uint4 (full 64-element K chunk)
        for (int i = tid; i < 1024; i += 256) {
            int rr = i >> 3, j = i & 7;
            long g = (long)(m0 + rr) * KP_ + kc + j * 8;
            uint32_t d = (uint32_t)(rr * XSTR + j * 8) * 2;
            *(uint4*)(smc + XOF_AHI + d) = *(const uint4*)(g_Ahi + g);
            *(uint4*)(smc + XOF_ALO + d) = *(const uint4*)(g_Alo + g);
        }
        // stage B hi/lo: 80 rows x 8 uint4
        for (int i = tid; i < 640; i += 256) {
            int rr = i >> 3, j = i & 7;
            long g = (long)(c0 + rr) * KP_ + kc + j * 8;
            uint32_t d = (uint32_t)(rr * XSTR + j * 8) * 2;
            *(uint4*)(smc + XOF_BHI + d) = *(const uint4*)(gBh + g);
            *(uint4*)(smc + XOF_BLO + d) = *(const uint4*)(gBl + g);
        }
        __syncthreads();
#pragma unroll
        for (int kk = 0; kk < 64; kk += 16) {
            uint32_t ah[2][4], al[2][4], bh[5][2], bl[5][2];
#pragma unroll
            for (int fm = 0; fm < 2; fm++) {
                uint32_t o = aOff + (uint32_t)(fm * 16 * XSTR + kk) * 2;
                LDSM_X4(ah[fm][0], ah[fm][1], ah[fm][2], ah[fm][3], sb + XOF_AHI + o);
                LDSM_X4(al[fm][0], al[fm][1], al[fm][2], al[fm][3], sb + XOF_ALO + o);
            }
#pragma unroll
            for (int fn = 0; fn < 5; fn++) {
                uint32_t o = bOff + (uint32_t)(fn * 8 * XSTR + kk) * 2;
                LDSM_X2(bh[fn][0], bh[fn][1], sb + XOF_BHI + o);
                LDSM_X2(bl[fn][0], bl[fn][1], sb + XOF_BLO + o);
            }
#pragma unroll
            for (int fm = 0; fm < 2; fm++)
#pragma unroll
                for (int fn = 0; fn < 5; fn++) {
                    MMA16816(acc[fm][fn], ah[fm], bh[fn]);
                    MMA16816(acc[fm][fn], al[fm], bh[fn]);
                    MMA16816(acc[fm][fn], ah[fm], bl[fn]);
                }
        }
    }

    // epilogue: c0/c1 at (m, n), c2/c3 at (m+8, n)
    int em = m0 + wm * 32 + (lane >> 2);
    int en = wn * 40 + (lane & 3) * 2;
#pragma unroll
    for (int fm = 0; fm < 2; fm++)
#pragma unroll
        for (int fn = 0; fn < 5; fn++) {
            int mg = em + fm * 16;
            int cg = en + fn * 8;
            float b0 = sbias[cg], b1 = sbias[cg + 1];
            float2 v0, v1;
            v0.x = acc[fm][fn][0] + b0; v0.y = acc[fm][fn][1] + b1;
            v1.x = acc[fm][fn][2] + b0; v1.y = acc[fm][fn][3] + b1;
            *(float2*)&g_zx[dir][(long)mg * GW_ + c0 + cg] = v0;
            *(float2*)&g_zx[dir][(long)(mg + 8) * GW_ + c0 + cg] = v1;
        }
}

// ---- K5: one word-LSTM step. 160 thr = 20 units x 8 batch-pairs. ----
__global__ __launch_bounds__(160)
void k_step(const int* __restrict__ seqlen, int t) {
    int dir = blockIdx.z;
    int b0  = blockIdx.y * 16;
    int u0  = blockIdx.x * 20;
    int p   = t & 1;
    __shared__ float hsm[16 * H_];
    int tid = threadIdx.x;
    for (int i = tid; i < 16 * H_; i += 160)
        hsm[i] = g_h[p][dir][(long)b0 * H_ + i];
    __syncthreads();

    int u   = u0 + tid % 20;
    int bp  = tid / 20;
    int bl0 = bp * 2, bl1 = bp * 2 + 1;
    const float* Wh = g_Wp[dir] + (long)EMB_ * GW_;
    float a00 = 0.f, a01 = 0.f, a02 = 0.f, a03 = 0.f;
    float a10 = 0.f, a11 = 0.f, a12 = 0.f, a13 = 0.f;
#pragma unroll 4
    for (int k = 0; k < H_; k++) {
        float4 w = *(const float4*)&Wh[(long)k * GW_ + u * 4];
        float h0 = hsm[bl0 * H_ + k];
        float h1 = hsm[bl1 * H_ + k];
        a00 += h0 * w.x; a01 += h0 * w.y; a02 += h0 * w.z; a03 += h0 * w.w;
        a10 += h1 * w.x; a11 += h1 * w.y; a12 += h1 * w.z; a13 += h1 * w.w;
    }
#pragma unroll
    for (int pi = 0; pi < 2; pi++) {
        int bl = bp * 2 + pi;
        int bg = b0 + bl;
        float A0 = pi ? a10 : a00, A1 = pi ? a11 : a01;
        float A2 = pi ? a12 : a02, A3 = pi ? a13 : a03;
        int len = seqlen[bg];
        int tt = dir ? ((t < len) ? (len - 1 - t) : t) : t;
        int n = bg * T_ + tt;
        float4 zx = *(const float4*)&g_zx[dir][(long)n * GW_ + u * 4];
        float iv = zx.x + A0, jv = zx.y + A1, fv = zx.z + A2, ov = zx.w + A3;
        int idx = bg * H_ + u;
        float cold = g_c[dir][idx];
        float hold = hsm[bl * H_ + u];
        float cnew = cold * sigf(fv + 1.f) + sigf(iv) * tanhfast(jv);
        float hnew = sigf(ov) * tanhfast(cnew);
        if (t >= len) { cnew = cold; hnew = hold; }
        g_c[dir][idx] = cnew;
        g_h[p ^ 1][dir][idx] = hnew;
    }
}

// ---- K6: projection + log_softmax + NLL mean ----
__global__ void k_final(const int* __restrict__ labels,
                        const float* __restrict__ Wp,
                        const float* __restrict__ bp,
                        float* __restrict__ out) {
    __shared__ float red[128];
    int b = threadIdx.x;
    float l0 = bp[0], l1 = bp[1], l2 = bp[2];
    for (int k = 0; k < H_; k++) {
        float v = g_c[0][b * H_ + k];
        l0 += v * Wp[k * 3 + 0]; l1 += v * Wp[k * 3 + 1]; l2 += v * Wp[k * 3 + 2];
    }
    for (int k = 0; k < H_; k++) {
        float v = g_c[1][b * H_ + k];
        l0 += v * Wp[(H_ + k) * 3 + 0]; l1 += v * Wp[(H_ + k) * 3 + 1]; l2 += v * Wp[(H_ + k) * 3 + 2];
    }
    float m = fmaxf(l0, fmaxf(l1, l2));
    float lse = m + logf(expf(l0 - m) + expf(l1 - m) + expf(l2 - m));
    int lab = labels[b];
    float lp = ((lab == 0) ? l0 : (lab == 1) ? l1 : l2) - lse;
    red[b] = lp;
    __syncthreads();
    for (int s = 64; s > 0; s >>= 1) {
        if (b < s) red[b] += red[b + s];
        __syncthreads();
    }
    if (b == 0) out[0] = -red[0] / 128.f;
}

extern "C" void kernel_launch(void* const* d_in, const int* in_sizes, int n_in,
                              void* d_out, int out_size) {
    (void)in_sizes; (void)n_in; (void)out_size;
    const int*   word_ids = (const int*)  d_in[0];
    const int*   seq_len  = (const int*)  d_in[1];
    const int*   char_ids = (const int*)  d_in[2];
    const int*   word_len = (const int*)  d_in[3];
    const int*   labels   = (const int*)  d_in[4];
    const float* word_emb = (const float*)d_in[5];
    const float* char_emb = (const float*)d_in[6];
    const float* Wc_fw    = (const float*)d_in[7];
    const float* bc_fw    = (const float*)d_in[8];
    const float* Wc_bw    = (const float*)d_in[9];
    const float* bc_bw    = (const float*)d_in[10];
    const float* Ww_fw    = (const float*)d_in[11];
    const float* bw_fw    = (const float*)d_in[12];
    const float* Ww_bw    = (const float*)d_in[13];
    const float* bw_bw    = (const float*)d_in[14];
    const float* W_proj   = (const float*)d_in[15];
    const float* b_proj   = (const float*)d_in[16];
    float* out = (float*)d_out;

    int char_smem = (DC_ * GC_ + 2 * 3300) * 4;       // 160KB + 26.4KB = 186400B
    cudaFuncSetAttribute(k_char, cudaFuncAttributeMaxDynamicSharedMemorySize, char_smem);
    cudaFuncSetAttribute(k_xmma, cudaFuncAttributeMaxDynamicSharedMemorySize, X_SMEM);

    k_embed<<<(BT_ * 75 + 255) / 256, 256>>>(word_ids, word_emb);
    k_permW<<<(2 * 800 * GW_ + 255) / 256, 256>>>(Ww_fw, bw_fw, Ww_bw, bw_bw);
    k_W2bf<<<(2 * GW_ * KP_ + 255) / 256, 256>>>(Ww_fw, Ww_bw);
    k_zcv<<<dim3(NV_, 2), GC_>>>(char_emb, Wc_fw, bc_fw, Wc_bw, bc_bw);
    k_char<<<dim3(BT_ / 32, 2), 800, char_smem>>>(char_ids, word_len, Wc_fw, Wc_bw);
    k_emb2bf<<<(int)(((long)BT_ * KP_ + 255) / 256), 256>>>();
    k_xmma<<<dim3(BT_ / 128, 15, 2), 256, X_SMEM>>>();
    for (int t = 0; t < T_; t++)
        k_step<<<dim3(15, 8, 2), 160>>>(seq_len, t);
    k_final<<<1, 128>>>(labels, W_proj, b_proj, out);
}

// round 8
// speedup vs baseline: 1.9142x; 1.6825x over previous
#include <cuda_runtime.h>
#include <cuda_bf16.h>
#include <cstdint>
#include <math.h>

#define B_   128
#define T_   256
#define L_   16
#define DW_  300
#define DC_  100
#define HC_  100
#define H_   300
#define NT_  3
#define NV_  101          // char vocab rows (NC+1)
#define EMB_ 500          // DW + 2*HC
#define KP_  512          // padded K for MMA
#define GW_  1200         // 4*H
#define GC_  400          // 4*HC
#define BT_  32768        // B*T
#define NBLK_STEP 120     // persistent step blocks (must be <= SM count at 1 blk/SM)

// ---------------- static device scratch (no runtime allocation) ----------------
__device__ __align__(16) float g_emb[BT_ * EMB_];        // [B*T, 500] word_emb | h_fw | h_bw
__device__ __align__(16) float g_zx[2][BT_ * GW_];       // word x-projection per dir (gate-permuted)
__device__ __align__(16) float g_Wp[2][800 * GW_];       // permuted Ww (col jp = u*4+g)
__device__ __align__(16) float g_bwp[2][GW_];            // permuted word bias
__device__ __align__(16) float g_zcv[2][NV_ * GC_];      // char vocab x-proj (+bias, permuted)
__device__ __align__(16) float g_h[2][2][B_ * H_];       // [parity][dir] word h (double buffer)
__device__ __align__(16) float g_c[2][B_ * H_];          // word cell state
// bf16 hi/lo operands for the x-projection MMA
__device__ __align__(16) __nv_bfloat16 g_Ahi[BT_ * KP_];
__device__ __align__(16) __nv_bfloat16 g_Alo[BT_ * KP_];
__device__ __align__(16) __nv_bfloat16 g_Bhi[2][GW_ * KP_];   // row jp, K-major
__device__ __align__(16) __nv_bfloat16 g_Blo[2][GW_ * KP_];
// grid barrier state for persistent step kernel
__device__ volatile unsigned g_barc;
__device__ volatile unsigned g_barp;

__device__ __forceinline__ float sigf(float x) {
    return __fdividef(1.f, 1.f + __expf(-x));
}
__device__ __forceinline__ float tanhfast(float x) {
    x = fminf(fmaxf(x, -15.f), 15.f);
    float e = __expf(2.f * x);
    return __fdividef(e - 1.f, e + 1.f);
}

// device-wide barrier: all threads fence, tid0 arrives; last arriver resets + bumps phase.
__device__ __forceinline__ void gbar(unsigned target, unsigned& phase) {
    __threadfence();
    __syncthreads();
    if (threadIdx.x == 0) {
        unsigned old = atomicAdd((unsigned*)&g_barc, 1u);
        if (old == target - 1u) {
            g_barc = 0u;
            __threadfence();
            atomicAdd((unsigned*)&g_barp, 1u);
        } else {
            while (g_barp <= phase) { }
        }
    }
    __syncthreads();
    phase++;
}

// ---------------- warp-level MMA helpers (base ISA: sm_80 ldmatrix/HMMA) ----------------
__device__ __forceinline__ uint32_t smem_u32(const void* p) {
    uint32_t a;
    asm("{ .reg .u64 t; cvta.to.shared.u64 t, %1; cvt.u32.u64 %0, t; }" : "=r"(a) : "l"(p));
    return a;
}
#define LDSM_X4(r0, r1, r2, r3, addr) \
    asm volatile("ldmatrix.sync.aligned.m8n8.x4.shared.b16 {%0,%1,%2,%3}, [%4];" \
                 : "=r"(r0), "=r"(r1), "=r"(r2), "=r"(r3) : "r"(addr))
#define LDSM_X2(r0, r1, addr) \
    asm volatile("ldmatrix.sync.aligned.m8n8.x2.shared.b16 {%0,%1}, [%2];" \
                 : "=r"(r0), "=r"(r1) : "r"(addr))
#define MMA16816(c, a, b) \
    asm volatile("mma.sync.aligned.m16n8k16.row.col.f32.bf16.bf16.f32 " \
                 "{%0,%1,%2,%3}, {%4,%5,%6,%7}, {%8,%9}, {%0,%1,%2,%3};" \
                 : "+f"((c)[0]), "+f"((c)[1]), "+f"((c)[2]), "+f"((c)[3]) \
                 : "r"((a)[0]), "r"((a)[1]), "r"((a)[2]), "r"((a)[3]), \
                   "r"((b)[0]), "r"((b)[1]))

// ---- K0: word embedding gather (float4) + zero-init word LSTM state + barrier reset ----
__global__ void k_embed(const int* __restrict__ word_ids,
                        const float* __restrict__ word_emb) {
    int i = blockIdx.x * blockDim.x + threadIdx.x;
    if (i == 0) { g_barc = 0u; g_barp = 0u; }
    if (i < BT_ * 75) {
        int n = i / 75, uq = i % 75;
        *(float4*)&g_emb[(long)n * EMB_ + uq * 4] =
            *(const float4*)&word_emb[(long)word_ids[n] * DW_ + uq * 4];
    }
    if (i < B_ * H_) {
        g_h[0][0][i] = 0.f; g_h[0][1][i] = 0.f;
        g_h[1][0][i] = 0.f; g_h[1][1][i] = 0.f;
    }
}

// ---- K1: permute word weights/bias to gate-interleaved columns jp = u*4+g ----
__global__ void k_permW(const float* __restrict__ Wf, const float* __restrict__ bf,
                        const float* __restrict__ Wb, const float* __restrict__ bb) {
    int i = blockIdx.x * blockDim.x + threadIdx.x;
    if (i < 2 * GW_) {
        int d = i / GW_, jp = i % GW_;
        const float* bs = d ? bb : bf;
        g_bwp[d][jp] = bs[(jp & 3) * H_ + (jp >> 2)];
    }
    if (i >= 2 * 800 * GW_) return;
    int d  = i / (800 * GW_);
    int r  = (i / GW_) % 800;
    int jp = i % GW_;
    const float* W = d ? Wb : Wf;
    g_Wp[d][(long)r * GW_ + jp] = W[(long)r * GW_ + (jp & 3) * H_ + (jp >> 2)];
}

// ---- K1b: bf16 hi/lo of word W (x-rows only), row jp, K-major ----
__global__ void k_W2bf(const float* __restrict__ Wf, const float* __restrict__ Wb) {
    int i = blockIdx.x * blockDim.x + threadIdx.x;
    if (i >= 2 * GW_ * KP_) return;
    int d  = i / (GW_ * KP_);
    int jp = (i / KP_) % GW_;
    int k  = i % KP_;
    float v = 0.f;
    if (k < EMB_) {
        const float* W = d ? Wb : Wf;
        v = W[(long)k * GW_ + (jp & 3) * H_ + (jp >> 2)];
    }
    __nv_bfloat16 hi = __float2bfloat16(v);
    __nv_bfloat16 lo = __float2bfloat16(v - __bfloat162float(hi));
    g_Bhi[d][(long)jp * KP_ + k] = hi;
    g_Blo[d][(long)jp * KP_ + k] = lo;
}

// ---- K2: char vocab x-projection ----
__global__ void k_zcv(const float* __restrict__ char_emb,
                      const float* __restrict__ Wf, const float* __restrict__ bf,
                      const float* __restrict__ Wb, const float* __restrict__ bb) {
    int v = blockIdx.x, d = blockIdx.y, jp = threadIdx.x;
    const float* W  = d ? Wb : Wf;
    const float* bs = d ? bb : bf;
    int col = (jp & 3) * HC_ + (jp >> 2);
    float acc = bs[col];
    for (int k = 0; k < DC_; k++)
        acc += char_emb[v * DC_ + k] * W[k * GC_ + col];
    g_zcv[d][v * GC_ + jp] = acc;
}

// ---- K3: char BiLSTM recurrence. lane = sequence, warp = unit-group. ----
__global__ __launch_bounds__(800, 1)
void k_char(const int* __restrict__ char_ids,
            const int* __restrict__ word_len,
            const float* __restrict__ Wf,
            const float* __restrict__ Wb) {
    int dir  = blockIdx.y;
    int seq0 = blockIdx.x * 32;
    const float* W = dir ? Wb : Wf;
    extern __shared__ float sm[];
    float* Ws  = sm;                         // [100*400] permuted Wh (160KB)
    float* hsA = sm + 40000;                 // [100*33] transposed h
    float* hsB = hsA + 3300;
    __shared__ int slen[32];
    __shared__ int scid[L_][32];
    int tid = threadIdx.x;                   // 800 = 25 uu x 32 s

    for (int i = tid; i < DC_ * GC_; i += 800) {
        int k = i / GC_, jp = i % GC_;
        Ws[i] = W[(DC_ + k) * GC_ + (jp & 3) * HC_ + (jp >> 2)];
    }
    for (int i = tid; i < 3300; i += 800) hsA[i] = 0.f;
    if (tid < 32) {
        int len = word_len[seq0 + tid];
        slen[tid] = len;
#pragma unroll
        for (int t = 0; t < L_; t++) {
            int tt = dir ? (len - 1 - t) : t;
            if (tt < 0) tt = 0;
            if (tt >= L_) tt = L_ - 1;
            scid[t][tid] = char_ids[(seq0 + tid) * L_ + tt];
        }
    }

    int s  = tid & 31;
    int uu = tid >> 5;               // 0..24, owns units uu*4 .. uu*4+3
    int u0 = uu * 4;
    float creg[4] = {0.f, 0.f, 0.f, 0.f};
    float hreg[4] = {0.f, 0.f, 0.f, 0.f};
    float* hr = hsA;
    float* hw = hsB;
    __syncthreads();

    for (int t = 0; t < L_; t++) {
        float acc[4][4];
#pragma unroll
        for (int j = 0; j < 4; j++) {
            acc[j][0] = 0.f; acc[j][1] = 0.f; acc[j][2] = 0.f; acc[j][3] = 0.f;
        }
#pragma unroll 2
        for (int k = 0; k < HC_; k++) {
            float hv = hr[k * 33 + s];
#pragma unroll
            for (int j = 0; j < 4; j++) {
                float4 w = *(const float4*)&Ws[k * GC_ + (u0 + j) * 4];
                acc[j][0] += hv * w.x; acc[j][1] += hv * w.y;
                acc[j][2] += hv * w.z; acc[j][3] += hv * w.w;
            }
        }
        int len = slen[s], cid = scid[t][s];
#pragma unroll
        for (int j = 0; j < 4; j++) {
            float4 zx = *(const float4*)&g_zcv[dir][cid * GC_ + (u0 + j) * 4];
            float iv = zx.x + acc[j][0], jv = zx.y + acc[j][1];
            float fv = zx.z + acc[j][2], ov = zx.w + acc[j][3];
            float c2 = creg[j] * sigf(fv + 1.f) + sigf(iv) * tanhfast(jv);
            float h2 = sigf(ov) * tanhfast(c2);
            if (t < len) { creg[j] = c2; hreg[j] = h2; }
            hw[(u0 + j) * 33 + s] = hreg[j];
        }
        __syncthreads();
        float* tmp = hr; hr = hw; hw = tmp;
    }
#pragma unroll
    for (int j = 0; j < 4; j++)
        g_emb[(long)(seq0 + s) * EMB_ + DW_ + dir * HC_ + u0 + j] = hreg[j];
}

// ---- K3b: split emb rows into bf16 hi/lo (padded K=512) ----
__global__ void k_emb2bf() {
    long i = (long)blockIdx.x * blockDim.x + threadIdx.x;
    if (i >= (long)BT_ * KP_) return;
    long n = i / KP_;
    int  k = (int)(i % KP_);
    float v = (k < EMB_) ? g_emb[n * EMB_ + k] : 0.f;
    __nv_bfloat16 hi = __float2bfloat16(v);
    __nv_bfloat16 lo = __float2bfloat16(v - __bfloat162float(hi));
    g_Ahi[i] = hi;
    g_Alo[i] = lo;
}

// ---- K4: x-projection via mma.sync bf16 hi/lo (3-pass). Block 128M x 80N. ----
#define XSTR 72
#define XOF_AHI 0
#define XOF_ALO 18432
#define XOF_BHI 36864
#define XOF_BLO 48384
#define XOF_BIAS 59904
#define X_SMEM  (XOF_BIAS + 320)

__global__ __launch_bounds__(256, 2)
void k_xmma() {
    extern __shared__ char smc[];
    int dir = blockIdx.z;
    int m0  = blockIdx.x * 128;
    int c0  = blockIdx.y * 80;
    int tid = threadIdx.x;
    int wid = tid >> 5, lane = tid & 31;
    int wm = wid & 3, wn = wid >> 2;         // 4 M-warps x 2 N-warps
    float* sbias = (float*)(smc + XOF_BIAS);

    for (int i = tid; i < 80; i += 256) sbias[i] = g_bwp[dir][c0 + i];

    uint32_t sb = smem_u32(smc);
    int r  = lane & 7, mi = lane >> 3;
    int aRow = wm * 32 + (mi & 1) * 8 + r;
    int aCol = (mi >> 1) * 8;
    int bRow = wn * 40 + r;
    int bCol = (mi & 1) * 8;
    uint32_t aOff = (uint32_t)(aRow * XSTR + aCol) * 2;
    uint32_t bOff = (uint32_t)(bRow * XSTR + bCol) * 2;

    float acc[2][5][4];
#pragma unroll
    for (int fm = 0; fm < 2; fm++)
#pragma unroll
        for (int fn = 0; fn < 5; fn++) {
            acc[fm][fn][0] = 0.f; acc[fm][fn][1] = 0.f;
            acc[fm][fn][2] = 0.f; acc[fm][fn][3] = 0.f;
        }

    const __nv_bfloat16* gBh = g_Bhi[dir];
    const __nv_bfloat16* gBl = g_Blo[dir];

    for (int ch = 0; ch < 8; ch++) {
        int kc = ch * 64;
        __syncthreads();
        for (int i = tid; i < 1024; i += 256) {
            int rr = i >> 3, j = i & 7;
            long g = (long)(m0 + rr) * KP_ + kc + j * 8;
            uint32_t d = (uint32_t)(rr * XSTR + j * 8) * 2;
            *(uint4*)(smc + XOF_AHI + d) = *(const uint4*)(g_Ahi + g);
            *(uint4*)(smc + XOF_ALO + d) = *(const uint4*)(g_Alo + g);
        }
        for (int i = tid; i < 640; i += 256) {
            int rr = i >> 3, j = i & 7;
            long g = (long)(c0 + rr) * KP_ + kc + j * 8;
            uint32_t d = (uint32_t)(rr * XSTR + j * 8) * 2;
            *(uint4*)(smc + XOF_BHI + d) = *(const uint4*)(gBh + g);
            *(uint4*)(smc + XOF_BLO + d) = *(const uint4*)(gBl + g);
        }
        __syncthreads();
#pragma unroll
        for (int kk = 0; kk < 64; kk += 16) {
            uint32_t ah[2][4], al[2][4], bh[5][2], bl[5][2];
#pragma unroll
            for (int fm = 0; fm < 2; fm++) {
                uint32_t o = aOff + (uint32_t)(fm * 16 * XSTR + kk) * 2;
                LDSM_X4(ah[fm][0], ah[fm][1], ah[fm][2], ah[fm][3], sb + XOF_AHI + o);
                LDSM_X4(al[fm][0], al[fm][1], al[fm][2], al[fm][3], sb + XOF_ALO + o);
            }
#pragma unroll
            for (int fn = 0; fn < 5; fn++) {
                uint32_t o = bOff + (uint32_t)(fn * 8 * XSTR + kk) * 2;
                LDSM_X2(bh[fn][0], bh[fn][1], sb + XOF_BHI + o);
                LDSM_X2(bl[fn][0], bl[fn][1], sb + XOF_BLO + o);
            }
#pragma unroll
            for (int fm = 0; fm < 2; fm++)
#pragma unroll
                for (int fn = 0; fn < 5; fn++) {
                    MMA16816(acc[fm][fn], ah[fm], bh[fn]);
                    MMA16816(acc[fm][fn], al[fm], bh[fn]);
                    MMA16816(acc[fm][fn], ah[fm], bl[fn]);
                }
        }
    }

    int em = m0 + wm * 32 + (lane >> 2);
    int en = wn * 40 + (lane & 3) * 2;
#pragma unroll
    for (int fm = 0; fm < 2; fm++)
#pragma unroll
        for (int fn = 0; fn < 5; fn++) {
            int mg = em + fm * 16;
            int cg = en + fn * 8;
            float b0 = sbias[cg], b1 = sbias[cg + 1];
            float2 v0, v1;
            v0.x = acc[fm][fn][0] + b0; v0.y = acc[fm][fn][1] + b1;
            v1.x = acc[fm][fn][2] + b0; v1.y = acc[fm][fn][3] + b1;
            *(float2*)&g_zx[dir][(long)mg * GW_ + c0 + cg] = v0;
            *(float2*)&g_zx[dir][(long)(mg + 8) * GW_ + c0 + cg] = v1;
        }
}

// ---- K5: persistent word LSTM. 120 blocks (15 u x 4 b x 2 dir), 320 thr. ----
// smem: Wh slice [300 x 80] (96KB) staged once + h stage [32 x 300] (38.4KB).
__global__ __launch_bounds__(320, 1)
void k_wstep(const int* __restrict__ seqlen) {
    int u0  = blockIdx.x * 20;
    int b0  = blockIdx.y * 32;
    int dir = blockIdx.z;
    extern __shared__ float s[];
    float* sW = s;                 // [300*80]
    float* hs = s + 24000;         // [32*300]
    int tid = threadIdx.x;

    const float* Wh = g_Wp[dir] + (long)EMB_ * GW_;
    for (int i = tid; i < 300 * 20; i += 320) {
        int k = i / 20, j = i % 20;
        *(float4*)&sW[k * 80 + j * 4] = *(const float4*)&Wh[(long)k * GW_ + (u0 + j) * 4];
    }

    int u   = u0 + tid % 20;
    int jl  = (tid % 20) * 4;
    int bp  = tid / 20;            // 0..15
    int bl0 = bp * 2, bl1 = bl0 + 1;
    int bg0 = b0 + bl0, bg1 = b0 + bl1;
    int len0 = seqlen[bg0], len1 = seqlen[bg1];
    float c0r = 0.f, c1r = 0.f;
    unsigned phase = 0;

    for (int t = 0; t < T_; t++) {
        int p = t & 1;
        if (t > 0) gbar(NBLK_STEP, phase);
        else __syncthreads();                 // sW staged
        // stage h for this b-tile (L2-coherent loads; L1 may be stale across steps)
        const float4* hsrc = (const float4*)&g_h[p][dir][(long)b0 * H_];
        for (int i = tid; i < 2400; i += 320)
            ((float4*)hs)[i] = __ldcg(hsrc + i);
        __syncthreads();

        float a00 = 0.f, a01 = 0.f, a02 = 0.f, a03 = 0.f;
        float a10 = 0.f, a11 = 0.f, a12 = 0.f, a13 = 0.f;
#pragma unroll 4
        for (int k = 0; k < H_; k++) {
            float4 w = *(const float4*)&sW[k * 80 + jl];
            float h0 = hs[bl0 * H_ + k];
            float h1 = hs[bl1 * H_ + k];
            a00 += h0 * w.x; a01 += h0 * w.y; a02 += h0 * w.z; a03 += h0 * w.w;
            a10 += h1 * w.x; a11 += h1 * w.y; a12 += h1 * w.z; a13 += h1 * w.w;
        }
        // batch 0
        {
            int tt = dir ? ((t < len0) ? (len0 - 1 - t) : t) : t;
            float4 zx = *(const float4*)&g_zx[dir][(long)(bg0 * T_ + tt) * GW_ + u * 4];
            float iv = zx.x + a00, jv = zx.y + a01, fv = zx.z + a02, ov = zx.w + a03;
            float cnew = c0r * sigf(fv + 1.f) + sigf(iv) * tanhfast(jv);
            float hnew = sigf(ov) * tanhfast(cnew);
            if (t >= len0) { cnew = c0r; hnew = hs[bl0 * H_ + u]; }
            c0r = cnew;
            g_h[p ^ 1][dir][bg0 * H_ + u] = hnew;
        }
        // batch 1
        {
            int tt = dir ? ((t < len1) ? (len1 - 1 - t) : t) : t;
            float4 zx = *(const float4*)&g_zx[dir][(long)(bg1 * T_ + tt) * GW_ + u * 4];
            float iv = zx.x + a10, jv = zx.y + a11, fv = zx.z + a12, ov = zx.w + a13;
            float cnew = c1r * sigf(fv + 1.f) + sigf(iv) * tanhfast(jv);
            float hnew = sigf(ov) * tanhfast(cnew);
            if (t >= len1) { cnew = c1r; hnew = hs[bl1 * H_ + u]; }
            c1r = cnew;
            g_h[p ^ 1][dir][bg1 * H_ + u] = hnew;
        }
    }
    g_c[dir][bg0 * H_ + u] = c0r;
    g_c[dir][bg1 * H_ + u] = c1r;
}

// ---- K6: projection + log_softmax + NLL mean ----
__global__ void k_final(const int* __restrict__ labels,
                        const float* __restrict__ Wp,
                        const float* __restrict__ bp,
                        float* __restrict__ out) {
    __shared__ float red[128];
    int b = threadIdx.x;
    float l0 = bp[0], l1 = bp[1], l2 = bp[2];
    for (int k = 0; k < H_; k++) {
        float v = g_c[0][b * H_ + k];
        l0 += v * Wp[k * 3 + 0]; l1 += v * Wp[k * 3 + 1]; l2 += v * Wp[k * 3 + 2];
    }
    for (int k = 0; k < H_; k++) {
        float v = g_c[1][b * H_ + k];
        l0 += v * Wp[(H_ + k) * 3 + 0]; l1 += v * Wp[(H_ + k) * 3 + 1]; l2 += v * Wp[(H_ + k) * 3 + 2];
    }
    float m = fmaxf(l0, fmaxf(l1, l2));
    float lse = m + logf(expf(l0 - m) + expf(l1 - m) + expf(l2 - m));
    int lab = labels[b];
    float lp = ((lab == 0) ? l0 : (lab == 1) ? l1 : l2) - lse;
    red[b] = lp;
    __syncthreads();
    for (int s = 64; s > 0; s >>= 1) {
        if (b < s) red[b] += red[b + s];
        __syncthreads();
    }
    if (b == 0) out[0] = -red[0] / 128.f;
}

extern "C" void kernel_launch(void* const* d_in, const int* in_sizes, int n_in,
                              void* d_out, int out_size) {
    (void)in_sizes; (void)n_in; (void)out_size;
    const int*   word_ids = (const int*)  d_in[0];
    const int*   seq_len  = (const int*)  d_in[1];
    const int*   char_ids = (const int*)  d_in[2];
    const int*   word_len = (const int*)  d_in[3];
    const int*   labels   = (const int*)  d_in[4];
    const float* word_emb = (const float*)d_in[5];
    const float* char_emb = (const float*)d_in[6];
    const float* Wc_fw    = (const float*)d_in[7];
    const float* bc_fw    = (const float*)d_in[8];
    const float* Wc_bw    = (const float*)d_in[9];
    const float* bc_bw    = (const float*)d_in[10];
    const float* Ww_fw    = (const float*)d_in[11];
    const float* bw_fw    = (const float*)d_in[12];
    const float* Ww_bw    = (const float*)d_in[13];
    const float* bw_bw    = (const float*)d_in[14];
    const float* W_proj   = (const float*)d_in[15];
    const float* b_proj   = (const float*)d_in[16];
    float* out = (float*)d_out;

    int char_smem = (DC_ * GC_ + 2 * 3300) * 4;       // 186400B
    int step_smem = (24000 + 9600) * 4;               // 134400B
    cudaFuncSetAttribute(k_char, cudaFuncAttributeMaxDynamicSharedMemorySize, char_smem);
    cudaFuncSetAttribute(k_xmma, cudaFuncAttributeMaxDynamicSharedMemorySize, X_SMEM);
    cudaFuncSetAttribute(k_wstep, cudaFuncAttributeMaxDynamicSharedMemorySize, step_smem);

    // order chosen so k_char is the 4th launch (the one ncu captures)
    k_embed<<<(BT_ * 75 + 255) / 256, 256>>>(word_ids, word_emb);
    k_permW<<<(2 * 800 * GW_ + 255) / 256, 256>>>(Ww_fw, bw_fw, Ww_bw, bw_bw);
    k_zcv<<<dim3(NV_, 2), GC_>>>(char_emb, Wc_fw, bc_fw, Wc_bw, bc_bw);
    k_char<<<dim3(BT_ / 32, 2), 800, char_smem>>>(char_ids, word_len, Wc_fw, Wc_bw);
    k_W2bf<<<(2 * GW_ * KP_ + 255) / 256, 256>>>(Ww_fw, Ww_bw);
    k_emb2bf<<<(int)(((long)BT_ * KP_ + 255) / 256), 256>>>();
    k_xmma<<<dim3(BT_ / 128, 15, 2), 256, X_SMEM>>>();
    k_wstep<<<dim3(15, 4, 2), 320, step_smem>>>(seq_len);
    k_final<<<1, 128>>>(labels, W_proj, b_proj, out);
}

// round 9
// speedup vs baseline: 2.1738x; 1.1356x over previous
#include <cuda_runtime.h>
#include <cuda_bf16.h>
#include <cstdint>
#include <math.h>

#define B_   128
#define T_   256
#define L_   16
#define DW_  300
#define DC_  100
#define HC_  100
#define H_   300
#define NT_  3
#define NV_  101          // char vocab rows (NC+1)
#define EMB_ 500          // DW + 2*HC
#define KP_  512          // padded K for MMA
#define GW_  1200         // 4*H
#define GC_  400          // 4*HC
#define BT_  32768        // B*T
#define GRP_BLK 15        // u-tile blocks per (b,dir) barrier group

// ---------------- static device scratch (no runtime allocation) ----------------
__device__ __align__(16) float g_emb[BT_ * EMB_];        // [B*T, 500] word_emb | h_fw | h_bw
__device__ __align__(16) float g_zx[2][BT_ * GW_];       // word x-projection per dir (gate-permuted)
__device__ __align__(16) float g_Wp[2][800 * GW_];       // permuted Ww (col jp = u*4+g)
__device__ __align__(16) float g_bwp[2][GW_];            // permuted word bias
__device__ __align__(16) float g_zcv[2][NV_ * GC_];      // char vocab x-proj (+bias, permuted)
__device__ __align__(16) float g_h[2][2][B_ * H_];       // [parity][dir] word h (double buffer)
__device__ __align__(16) float g_c[2][B_ * H_];          // word cell state
// bf16 hi/lo operands for the x-projection MMA
__device__ __align__(16) __nv_bfloat16 g_Ahi[BT_ * KP_];
__device__ __align__(16) __nv_bfloat16 g_Alo[BT_ * KP_];
__device__ __align__(16) __nv_bfloat16 g_Bhi[2][GW_ * KP_];   // row jp, K-major
__device__ __align__(16) __nv_bfloat16 g_Blo[2][GW_ * KP_];
// per-group grid barrier state for persistent step kernel (8 groups of 15 blocks)
__device__ volatile unsigned g_barc8[8];
__device__ volatile unsigned g_barp8[8];

__device__ __forceinline__ float sigf(float x) {
    return __fdividef(1.f, 1.f + __expf(-x));
}
__device__ __forceinline__ float tanhfast(float x) {
    x = fminf(fmaxf(x, -15.f), 15.f);
    float e = __expf(2.f * x);
    return __fdividef(e - 1.f, e + 1.f);
}

// group barrier: all threads fence, tid0 arrives; last arriver resets + bumps phase.
__device__ __forceinline__ void gbar_grp(int g, unsigned& phase) {
    __threadfence();
    __syncthreads();
    if (threadIdx.x == 0) {
        unsigned old = atomicAdd((unsigned*)&g_barc8[g], 1u);
        if (old == GRP_BLK - 1u) {
            g_barc8[g] = 0u;
            __threadfence();
            atomicAdd((unsigned*)&g_barp8[g], 1u);
        } else {
            while (g_barp8[g] <= phase) { }
        }
    }
    __syncthreads();
    phase++;
}

// ---------------- warp-level MMA helpers (base ISA: sm_80 ldmatrix/HMMA) ----------------
__device__ __forceinline__ uint32_t smem_u32(const void* p) {
    uint32_t a;
    asm("{ .reg .u64 t; cvta.to.shared.u64 t, %1; cvt.u32.u64 %0, t; }" : "=r"(a) : "l"(p));
    return a;
}
#define LDSM_X4(r0, r1, r2, r3, addr) \
    asm volatile("ldmatrix.sync.aligned.m8n8.x4.shared.b16 {%0,%1,%2,%3}, [%4];" \
                 : "=r"(r0), "=r"(r1), "=r"(r2), "=r"(r3) : "r"(addr))
#define LDSM_X2(r0, r1, addr) \
    asm volatile("ldmatrix.sync.aligned.m8n8.x2.shared.b16 {%0,%1}, [%2];" \
                 : "=r"(r0), "=r"(r1) : "r"(addr))
#define MMA16816(c, a, b) \
    asm volatile("mma.sync.aligned.m16n8k16.row.col.f32.bf16.bf16.f32 " \
                 "{%0,%1,%2,%3}, {%4,%5,%6,%7}, {%8,%9}, {%0,%1,%2,%3};" \
                 : "+f"((c)[0]), "+f"((c)[1]), "+f"((c)[2]), "+f"((c)[3]) \
                 : "r"((a)[0]), "r"((a)[1]), "r"((a)[2]), "r"((a)[3]), \
                   "r"((b)[0]), "r"((b)[1]))

// ---- K0: word embedding gather (float4) + zero-init word LSTM state + barrier reset ----
__global__ void k_embed(const int* __restrict__ word_ids,
                        const float* __restrict__ word_emb) {
    int i = blockIdx.x * blockDim.x + threadIdx.x;
    if (i < 8) { g_barc8[i] = 0u; g_barp8[i] = 0u; }
    if (i < BT_ * 75) {
        int n = i / 75, uq = i % 75;
        *(float4*)&g_emb[(long)n * EMB_ + uq * 4] =
            *(const float4*)&word_emb[(long)word_ids[n] * DW_ + uq * 4];
    }
    if (i < B_ * H_) {
        g_h[0][0][i] = 0.f; g_h[0][1][i] = 0.f;
        g_h[1][0][i] = 0.f; g_h[1][1][i] = 0.f;
    }
}

// ---- K1: permute word weights/bias to gate-interleaved columns jp = u*4+g ----
__global__ void k_permW(const float* __restrict__ Wf, const float* __restrict__ bf,
                        const float* __restrict__ Wb, const float* __restrict__ bb) {
    int i = blockIdx.x * blockDim.x + threadIdx.x;
    if (i < 2 * GW_) {
        int d = i / GW_, jp = i % GW_;
        const float* bs = d ? bb : bf;
        g_bwp[d][jp] = bs[(jp & 3) * H_ + (jp >> 2)];
    }
    if (i >= 2 * 800 * GW_) return;
    int d  = i / (800 * GW_);
    int r  = (i / GW_) % 800;
    int jp = i % GW_;
    const float* W = d ? Wb : Wf;
    g_Wp[d][(long)r * GW_ + jp] = W[(long)r * GW_ + (jp & 3) * H_ + (jp >> 2)];
}

// ---- K1b: bf16 hi/lo of word W (x-rows only), row jp, K-major ----
__global__ void k_W2bf(const float* __restrict__ Wf, const float* __restrict__ Wb) {
    int i = blockIdx.x * blockDim.x + threadIdx.x;
    if (i >= 2 * GW_ * KP_) return;
    int d  = i / (GW_ * KP_);
    int jp = (i / KP_) % GW_;
    int k  = i % KP_;
    float v = 0.f;
    if (k < EMB_) {
        const float* W = d ? Wb : Wf;
        v = W[(long)k * GW_ + (jp & 3) * H_ + (jp >> 2)];
    }
    __nv_bfloat16 hi = __float2bfloat16(v);
    __nv_bfloat16 lo = __float2bfloat16(v - __bfloat162float(hi));
    g_Bhi[d][(long)jp * KP_ + k] = hi;
    g_Blo[d][(long)jp * KP_ + k] = lo;
}

// ---- K2: char vocab x-projection ----
__global__ void k_zcv(const float* __restrict__ char_emb,
                      const float* __restrict__ Wf, const float* __restrict__ bf,
                      const float* __restrict__ Wb, const float* __restrict__ bb) {
    int v = blockIdx.x, d = blockIdx.y, jp = threadIdx.x;
    const float* W  = d ? Wb : Wf;
    const float* bs = d ? bb : bf;
    int col = (jp & 3) * HC_ + (jp >> 2);
    float acc = bs[col];
    for (int k = 0; k < DC_; k++)
        acc += char_emb[v * DC_ + k] * W[k * GC_ + col];
    g_zcv[d][v * GC_ + jp] = acc;
}

// ---- K3: char BiLSTM recurrence. 800 threads, 4 seqs/thread,
//          k-unrolled x4 with float4 h loads (best measured instruction mix). ----
__global__ __launch_bounds__(800, 1)
void k_char(const int* __restrict__ char_ids,
            const int* __restrict__ word_len,
            const float* __restrict__ Wf,
            const float* __restrict__ Wb) {
    int dir  = blockIdx.y;
    int seq0 = blockIdx.x * 32;
    const float* W = dir ? Wb : Wf;
    extern __shared__ float sm[];
    float* Ws  = sm;                         // [100*400] permuted Wh (160KB)
    float* hsA = sm + 40000;                 // [32*100]
    float* hsB = hsA + 32 * HC_;
    __shared__ int slen[32];
    __shared__ int scid[L_][32];
    int tid = threadIdx.x;                   // 800 = 8 q-groups x 100 units

    for (int i = tid; i < DC_ * GC_; i += 800) {
        int k = i / GC_, jp = i % GC_;
        Ws[i] = W[(DC_ + k) * GC_ + (jp & 3) * HC_ + (jp >> 2)];
    }
    for (int i = tid; i < 32 * HC_; i += 800) hsA[i] = 0.f;
    if (tid < 32) {
        int len = word_len[seq0 + tid];
        slen[tid] = len;
#pragma unroll
        for (int t = 0; t < L_; t++) {
            int tt = dir ? (len - 1 - t) : t;
            if (tt < 0) tt = 0;
            if (tt >= L_) tt = L_ - 1;
            scid[t][tid] = char_ids[(seq0 + tid) * L_ + tt];
        }
    }

    int q = tid / HC_;               // 0..7 -> owns seqs q*4 .. q*4+3
    int u = tid % HC_;
    int jp0 = u * 4;
    float creg[4] = {0.f, 0.f, 0.f, 0.f};
    float hreg[4] = {0.f, 0.f, 0.f, 0.f};
    float* hr = hsA;
    float* hw = hsB;
    __syncthreads();

    for (int t = 0; t < L_; t++) {
        float acc[4][4];
#pragma unroll
        for (int a = 0; a < 4; a++) {
            acc[a][0] = 0.f; acc[a][1] = 0.f; acc[a][2] = 0.f; acc[a][3] = 0.f;
        }
#pragma unroll 5
        for (int k = 0; k < HC_; k += 4) {
            float4 w0 = *(const float4*)&Ws[(k    ) * GC_ + jp0];
            float4 w1 = *(const float4*)&Ws[(k + 1) * GC_ + jp0];
            float4 w2 = *(const float4*)&Ws[(k + 2) * GC_ + jp0];
            float4 w3 = *(const float4*)&Ws[(k + 3) * GC_ + jp0];
#pragma unroll
            for (int a = 0; a < 4; a++) {
                float4 hv = *(const float4*)&hr[(q * 4 + a) * HC_ + k];
                acc[a][0] += hv.x * w0.x + hv.y * w1.x + hv.z * w2.x + hv.w * w3.x;
                acc[a][1] += hv.x * w0.y + hv.y * w1.y + hv.z * w2.y + hv.w * w3.y;
                acc[a][2] += hv.x * w0.z + hv.y * w1.z + hv.z * w2.z + hv.w * w3.z;
                acc[a][3] += hv.x * w0.w + hv.y * w1.w + hv.z * w2.w + hv.w * w3.w;
            }
        }
#pragma unroll
        for (int a = 0; a < 4; a++) {
            int s = q * 4 + a;
            float4 zx = *(const float4*)&g_zcv[dir][scid[t][s] * GC_ + jp0];
            float iv = zx.x + acc[a][0], jv = zx.y + acc[a][1];
            float fv = zx.z + acc[a][2], ov = zx.w + acc[a][3];
            float c2 = creg[a] * sigf(fv + 1.f) + sigf(iv) * tanhfast(jv);
            float h2 = sigf(ov) * tanhfast(c2);
            if (t < slen[s]) { creg[a] = c2; hreg[a] = h2; }
            hw[s * HC_ + u] = hreg[a];
        }
        __syncthreads();
        float* tmp = hr; hr = hw; hw = tmp;
    }
#pragma unroll
    for (int a = 0; a < 4; a++) {
        int n = seq0 + q * 4 + a;
        g_emb[(long)n * EMB_ + DW_ + dir * HC_ + u] = hreg[a];
    }
}

// ---- K3b: split emb rows into bf16 hi/lo (padded K=512) ----
__global__ void k_emb2bf() {
    long i = (long)blockIdx.x * blockDim.x + threadIdx.x;
    if (i >= (long)BT_ * KP_) return;
    long n = i / KP_;
    int  k = (int)(i % KP_);
    float v = (k < EMB_) ? g_emb[n * EMB_ + k] : 0.f;
    __nv_bfloat16 hi = __float2bfloat16(v);
    __nv_bfloat16 lo = __float2bfloat16(v - __bfloat162float(hi));
    g_Ahi[i] = hi;
    g_Alo[i] = lo;
}

// ---- K4: x-projection via mma.sync bf16 hi/lo (3-pass). Block 128M x 80N. ----
#define XSTR 72
#define XOF_AHI 0
#define XOF_ALO 18432
#define XOF_BHI 36864
#define XOF_BLO 48384
#define XOF_BIAS 59904
#define X_SMEM  (XOF_BIAS + 320)

__global__ __launch_bounds__(256, 2)
void k_xmma() {
    extern __shared__ char smc[];
    int dir = blockIdx.z;
    int m0  = blockIdx.x * 128;
    int c0  = blockIdx.y * 80;
    int tid = threadIdx.x;
    int wid = tid >> 5, lane = tid & 31;
    int wm = wid & 3, wn = wid >> 2;         // 4 M-warps x 2 N-warps
    float* sbias = (float*)(smc + XOF_BIAS);

    for (int i = tid; i < 80; i += 256) sbias[i] = g_bwp[dir][c0 + i];

    uint32_t sb = smem_u32(smc);
    int r  = lane & 7, mi = lane >> 3;
    int aRow = wm * 32 + (mi & 1) * 8 + r;
    int aCol = (mi >> 1) * 8;
    int bRow = wn * 40 + r;
    int bCol = (mi & 1) * 8;
    uint32_t aOff = (uint32_t)(aRow * XSTR + aCol) * 2;
    uint32_t bOff = (uint32_t)(bRow * XSTR + bCol) * 2;

    float acc[2][5][4];
#pragma unroll
    for (int fm = 0; fm < 2; fm++)
#pragma unroll
        for (int fn = 0; fn < 5; fn++) {
            acc[fm][fn][0] = 0.f; acc[fm][fn][1] = 0.f;
            acc[fm][fn][2] = 0.f; acc[fm][fn][3] = 0.f;
        }

    const __nv_bfloat16* gBh = g_Bhi[dir];
    const __nv_bfloat16* gBl = g_Blo[dir];

    for (int ch = 0; ch < 8; ch++) {
        int kc = ch * 64;
        __syncthreads();
        for (int i = tid; i < 1024; i += 256) {
            int rr = i >> 3, j = i & 7;
            long g = (long)(m0 + rr) * KP_ + kc + j * 8;
            uint32_t d = (uint32_t)(rr * XSTR + j * 8) * 2;
            *(uint4*)(smc + XOF_AHI + d) = *(const uint4*)(g_Ahi + g);
            *(uint4*)(smc + XOF_ALO + d) = *(const uint4*)(g_Alo + g);
        }
        for (int i = tid; i < 640; i += 256) {
            int rr = i >> 3, j = i & 7;
            long g = (long)(c0 + rr) * KP_ + kc + j * 8;
            uint32_t d = (uint32_t)(rr * XSTR + j * 8) * 2;
            *(uint4*)(smc + XOF_BHI + d) = *(const uint4*)(gBh + g);
            *(uint4*)(smc + XOF_BLO + d) = *(const uint4*)(gBl + g);
        }
        __syncthreads();
#pragma unroll
        for (int kk = 0; kk < 64; kk += 16) {
            uint32_t ah[2][4], al[2][4], bh[5][2], bl[5][2];
#pragma unroll
            for (int fm = 0; fm < 2; fm++) {
                uint32_t o = aOff + (uint32_t)(fm * 16 * XSTR + kk) * 2;
                LDSM_X4(ah[fm][0], ah[fm][1], ah[fm][2], ah[fm][3], sb + XOF_AHI + o);
                LDSM_X4(al[fm][0], al[fm][1], al[fm][2], al[fm][3], sb + XOF_ALO + o);
            }
#pragma unroll
            for (int fn = 0; fn < 5; fn++) {
                uint32_t o = bOff + (uint32_t)(fn * 8 * XSTR + kk) * 2;
                LDSM_X2(bh[fn][0], bh[fn][1], sb + XOF_BHI + o);
                LDSM_X2(bl[fn][0], bl[fn][1], sb + XOF_BLO + o);
            }
#pragma unroll
            for (int fm = 0; fm < 2; fm++)
#pragma unroll
                for (int fn = 0; fn < 5; fn++) {
                    MMA16816(acc[fm][fn], ah[fm], bh[fn]);
                    MMA16816(acc[fm][fn], al[fm], bh[fn]);
                    MMA16816(acc[fm][fn], ah[fm], bl[fn]);
                }
        }
    }

    int em = m0 + wm * 32 + (lane >> 2);
    int en = wn * 40 + (lane & 3) * 2;
#pragma unroll
    for (int fm = 0; fm < 2; fm++)
#pragma unroll
        for (int fn = 0; fn < 5; fn++) {
            int mg = em + fm * 16;
            int cg = en + fn * 8;
            float b0 = sbias[cg], b1 = sbias[cg + 1];
            float2 v0, v1;
            v0.x = acc[fm][fn][0] + b0; v0.y = acc[fm][fn][1] + b1;
            v1.x = acc[fm][fn][2] + b0; v1.y = acc[fm][fn][3] + b1;
            *(float2*)&g_zx[dir][(long)mg * GW_ + c0 + cg] = v0;
            *(float2*)&g_zx[dir][(long)(mg + 8) * GW_ + c0 + cg] = v1;
        }
}

// ---- K5: persistent word LSTM. 120 blocks (15 u x 4 b x 2 dir), 320 thr. ----
// Barrier groups: the 15 u-blocks sharing (b-tile, dir) sync among themselves.
__global__ __launch_bounds__(320, 1)
void k_wstep(const int* __restrict__ seqlen) {
    int u0  = blockIdx.x * 20;
    int b0  = blockIdx.y * 32;
    int dir = blockIdx.z;
    int grp = blockIdx.y * 2 + blockIdx.z;   // 0..7
    extern __shared__ float s[];
    float* sW = s;                 // [300*80]
    float* hs = s + 24000;         // [32*300]
    int tid = threadIdx.x;

    const float* Wh = g_Wp[dir] + (long)EMB_ * GW_;
    for (int i = tid; i < 300 * 20; i += 320) {
        int k = i / 20, j = i % 20;
        *(float4*)&sW[k * 80 + j * 4] = *(const float4*)&Wh[(long)k * GW_ + (u0 + j) * 4];
    }

    int u   = u0 + tid % 20;
    int jl  = (tid % 20) * 4;
    int bp  = tid / 20;            // 0..15
    int bl0 = bp * 2, bl1 = bl0 + 1;
    int bg0 = b0 + bl0, bg1 = b0 + bl1;
    int len0 = seqlen[bg0], len1 = seqlen[bg1];
    float c0r = 0.f, c1r = 0.f;
    unsigned phase = 0;

    for (int t = 0; t < T_; t++) {
        int p = t & 1;
        if (t > 0) gbar_grp(grp, phase);
        else __syncthreads();                 // sW staged
        const float4* hsrc = (const float4*)&g_h[p][dir][(long)b0 * H_];
        for (int i = tid; i < 2400; i += 320)
            ((float4*)hs)[i] = __ldcg(hsrc + i);
        __syncthreads();

        float a00 = 0.f, a01 = 0.f, a02 = 0.f, a03 = 0.f;
        float a10 = 0.f, a11 = 0.f, a12 = 0.f, a13 = 0.f;
#pragma unroll 4
        for (int k = 0; k < H_; k++) {
            float4 w = *(const float4*)&sW[k * 80 + jl];
            float h0 = hs[bl0 * H_ + k];
            float h1 = hs[bl1 * H_ + k];
            a00 += h0 * w.x; a01 += h0 * w.y; a02 += h0 * w.z; a03 += h0 * w.w;
            a10 += h1 * w.x; a11 += h1 * w.y; a12 += h1 * w.z; a13 += h1 * w.w;
        }
        {
            int tt = dir ? ((t < len0) ? (len0 - 1 - t) : t) : t;
            float4 zx = *(const float4*)&g_zx[dir][(long)(bg0 * T_ + tt) * GW_ + u * 4];
            float iv = zx.x + a00, jv = zx.y + a01, fv = zx.z + a02, ov = zx.w + a03;
            float cnew = c0r * sigf(fv + 1.f) + sigf(iv) * tanhfast(jv);
            float hnew = sigf(ov) * tanhfast(cnew);
            if (t >= len0) { cnew = c0r; hnew = hs[bl0 * H_ + u]; }
            c0r = cnew;
            g_h[p ^ 1][dir][bg0 * H_ + u] = hnew;
        }
        {
            int tt = dir ? ((t < len1) ? (len1 - 1 - t) : t) : t;
            float4 zx = *(const float4*)&g_zx[dir][(long)(bg1 * T_ + tt) * GW_ + u * 4];
            float iv = zx.x + a10, jv = zx.y + a11, fv = zx.z + a12, ov = zx.w + a13;
            float cnew = c1r * sigf(fv + 1.f) + sigf(iv) * tanhfast(jv);
            float hnew = sigf(ov) * tanhfast(cnew);
            if (t >= len1) { cnew = c1r; hnew = hs[bl1 * H_ + u]; }
            c1r = cnew;
            g_h[p ^ 1][dir][bg1 * H_ + u] = hnew;
        }
    }
    g_c[dir][bg0 * H_ + u] = c0r;
    g_c[dir][bg1 * H_ + u] = c1r;
}

// ---- K6: projection + log_softmax + NLL mean ----
__global__ void k_final(const int* __restrict__ labels,
                        const float* __restrict__ Wp,
                        const float* __restrict__ bp,
                        float* __restrict__ out) {
    __shared__ float red[128];
    int b = threadIdx.x;
    float l0 = bp[0], l1 = bp[1], l2 = bp[2];
    for (int k = 0; k < H_; k++) {
        float v = g_c[0][b * H_ + k];
        l0 += v * Wp[k * 3 + 0]; l1 += v * Wp[k * 3 + 1]; l2 += v * Wp[k * 3 + 2];
    }
    for (int k = 0; k < H_; k++) {
        float v = g_c[1][b * H_ + k];
        l0 += v * Wp[(H_ + k) * 3 + 0]; l1 += v * Wp[(H_ + k) * 3 + 1]; l2 += v * Wp[(H_ + k) * 3 + 2];
    }
    float m = fmaxf(l0, fmaxf(l1, l2));
    float lse = m + logf(expf(l0 - m) + expf(l1 - m) + expf(l2 - m));
    int lab = labels[b];
    float lp = ((lab == 0) ? l0 : (lab == 1) ? l1 : l2) - lse;
    red[b] = lp;
    __syncthreads();
    for (int s = 64; s > 0; s >>= 1) {
        if (b < s) red[b] += red[b + s];
        __syncthreads();
    }
    if (b == 0) out[0] = -red[0] / 128.f;
}

extern "C" void kernel_launch(void* const* d_in, const int* in_sizes, int n_in,
                              void* d_out, int out_size) {
    (void)in_sizes; (void)n_in; (void)out_size;
    const int*   word_ids = (const int*)  d_in[0];
    const int*   seq_len  = (const int*)  d_in[1];
    const int*   char_ids = (const int*)  d_in[2];
    const int*   word_len = (const int*)  d_in[3];
    const int*   labels   = (const int*)  d_in[4];
    const float* word_emb = (const float*)d_in[5];
    const float* char_emb = (const float*)d_in[6];
    const float* Wc_fw    = (const float*)d_in[7];
    const float* bc_fw    = (const float*)d_in[8];
    const float* Wc_bw    = (const float*)d_in[9];
    const float* bc_bw    = (const float*)d_in[10];
    const float* Ww_fw    = (const float*)d_in[11];
    const float* bw_fw    = (const float*)d_in[12];
    const float* Ww_bw    = (const float*)d_in[13];
    const float* bw_bw    = (const float*)d_in[14];
    const float* W_proj   = (const float*)d_in[15];
    const float* b_proj   = (const float*)d_in[16];
    float* out = (float*)d_out;

    int char_smem = (DC_ * GC_ + 2 * 32 * HC_) * 4;   // 185600B
    int step_smem = (24000 + 9600) * 4;               // 134400B
    cudaFuncSetAttribute(k_char, cudaFuncAttributeMaxDynamicSharedMemorySize, char_smem);
    cudaFuncSetAttribute(k_xmma, cudaFuncAttributeMaxDynamicSharedMemorySize, X_SMEM);
    cudaFuncSetAttribute(k_wstep, cudaFuncAttributeMaxDynamicSharedMemorySize, step_smem);

    // order chosen so k_char is the 4th launch (the one ncu captures)
    k_embed<<<(BT_ * 75 + 255) / 256, 256>>>(word_ids, word_emb);
    k_permW<<<(2 * 800 * GW_ + 255) / 256, 256>>>(Ww_fw, bw_fw, Ww_bw, bw_bw);
    k_zcv<<<dim3(NV_, 2), GC_>>>(char_emb, Wc_fw, bc_fw, Wc_bw, bc_bw);
    k_char<<<dim3(BT_ / 32, 2), 800, char_smem>>>(char_ids, word_len, Wc_fw, Wc_bw);
    k_W2bf<<<(2 * GW_ * KP_ + 255) / 256, 256>>>(Ww_fw, Ww_bw);
    k_emb2bf<<<(int)(((long)BT_ * KP_ + 255) / 256), 256>>>();
    k_xmma<<<dim3(BT_ / 128, 15, 2), 256, X_SMEM>>>();
    k_wstep<<<dim3(15, 4, 2), 320, step_smem>>>(seq_len);
    k_final<<<1, 128>>>(labels, W_proj, b_proj, out);
}